// round 12
// baseline (speedup 1.0000x reference)
#include <cuda_runtime.h>
#include <cstddef>

#define OUT0 131072 // 1024*128, offset of out_dis in d_out

typedef unsigned long long u64;

// ---------------- scratch (device globals; no allocation allowed) -------------
__device__ float g_qk[1024 * 512];            // [B*L][INNER]
__device__ float g_cqk[8192 * 512];           // [B*P][INNER]
__device__ float g_cv[8192 * 512];            // [B*P][INNER]
__device__ float g_sim[16 * 16 * 64 * 512];   // [b][h][l][p] (scaled)
__device__ float g_probs[16 * 32 * 64 * 512]; // [b][c][l][p] (only c<16 written)
__device__ float g_outpre[1024 * 512];        // partial 0 (p 0..255)
__device__ float g_outpre2[1024 * 512];       // partial 1 (p 256..511)

// mish(x) = x*tanh(softplus(x)) = x * u/(u+2), u = e^x*(e^x+2)  (exact identity)
__device__ __forceinline__ float mishf(float x) {
    float t = __expf(fminf(x, 8.0f));
    float u = t * (t + 2.0f);
    return x * __fdividef(u, u + 2.0f);
}

__device__ __forceinline__ float tf32r(float x) {
    unsigned u;
    asm("cvt.rna.tf32.f32 %0, %1;" : "=r"(u) : "f"(x));
    return __uint_as_float(u);
}

__device__ __forceinline__ void mma8(float* c, unsigned a0, unsigned a1,
                                     unsigned a2, unsigned a3,
                                     unsigned b0, unsigned b1) {
    asm volatile(
        "mma.sync.aligned.m16n8k8.row.col.f32.tf32.tf32.f32 "
        "{%0,%1,%2,%3},{%4,%5,%6,%7},{%8,%9},{%0,%1,%2,%3};"
        : "+f"(c[0]), "+f"(c[1]), "+f"(c[2]), "+f"(c[3])
        : "r"(a0), "r"(a1), "r"(a2), "r"(a3), "r"(b0), "r"(b1));
}

// ---- packed f32x2 helpers (Blackwell FFMA2 — only reachable via PTX) ---------
__device__ __forceinline__ u64 ffma2(u64 a, u64 b, u64 c) {
    u64 d;
    asm("fma.rn.f32x2 %0, %1, %2, %3;" : "=l"(d) : "l"(a), "l"(b), "l"(c));
    return d;
}
__device__ __forceinline__ u64 pk2(float x, float y) {
    u64 r;
    asm("mov.b64 %0, {%1, %2};" : "=l"(r) : "f"(x), "f"(y));
    return r;
}
__device__ __forceinline__ float2 up2(u64 v) {
    float2 r;
    asm("mov.b64 {%0, %1}, %2;" : "=f"(r.x), "=f"(r.y) : "l"(v));
    return r;
}

// ------ unified tf32 GEMM: blocks 0..511 cqk|cv (K=256), 512..543 qk (K=128) --
// Double-buffered smem (ping-pong) + register prefetch of the next k-slab.
#define TG_AS(buf, r, k) tg_sm[(buf) * 4608 + (r) * 36 + (k)]
#define TG_BS(buf, k, n) tg_sm[9216 + (buf) * 4352 + (k) * 136 + (n)]
#define TG_SM_BYTES ((9216 + 8704) * 4)

__global__ void __launch_bounds__(256, 2) tgemm_all(
    const float* __restrict__ ctx, const float* __restrict__ hlig,
    const float* __restrict__ w_cqk, const float* __restrict__ w_cv,
    const float* __restrict__ w_qk,
    float* __restrict__ cqk, float* __restrict__ cv, float* __restrict__ qk)
{
    extern __shared__ float tg_sm[];
    const int tid = threadIdx.x;
    const int lane = tid & 31, warp = tid >> 5;
    const int wm = warp >> 1, wn = warp & 1;
    const int g = lane >> 2, t = lane & 3;
    const int N = 512;

    int bid = blockIdx.x;
    const float* A; const float* Bm; float* C;
    int row0, col0, K;
    if (bid < 512) {
        row0 = (bid >> 3) * 128; col0 = (bid & 7) * 128;
        A = ctx; K = 256;
        if (col0 >= 512) { Bm = w_cv; C = cv; col0 -= 512; }
        else             { Bm = w_cqk; C = cqk; }
    } else {
        int b2 = bid - 512;
        row0 = (b2 >> 2) * 128; col0 = (b2 & 3) * 128;
        A = hlig; Bm = w_qk; C = qk; K = 128;
    }

    float acc[2][8][4];
#pragma unroll
    for (int mt = 0; mt < 2; ++mt)
#pragma unroll
        for (int nt = 0; nt < 8; ++nt)
#pragma unroll
            for (int q = 0; q < 4; ++q) acc[mt][nt][q] = 0.f;

    float4 va[4], vb[4];
    // prologue: load + stage slab 0 into buffer 0
#pragma unroll
    for (int i = 0; i < 4; ++i) {
        int f4 = tid + i * 256;
        int r = f4 >> 3, kc = (f4 & 7) * 4;
        va[i] = *(const float4*)&A[(size_t)(row0 + r) * K + kc];
        int kk = f4 >> 5, nc = (f4 & 31) * 4;
        vb[i] = *(const float4*)&Bm[(size_t)kk * N + col0 + nc];
    }
#pragma unroll
    for (int i = 0; i < 4; ++i) {
        int f4 = tid + i * 256;
        int r = f4 >> 3, kc = (f4 & 7) * 4;
        TG_AS(0, r, kc + 0) = tf32r(va[i].x);
        TG_AS(0, r, kc + 1) = tf32r(va[i].y);
        TG_AS(0, r, kc + 2) = tf32r(va[i].z);
        TG_AS(0, r, kc + 3) = tf32r(va[i].w);
        int kk = f4 >> 5, nc = (f4 & 31) * 4;
        TG_BS(0, kk, nc + 0) = tf32r(vb[i].x);
        TG_BS(0, kk, nc + 1) = tf32r(vb[i].y);
        TG_BS(0, kk, nc + 2) = tf32r(vb[i].z);
        TG_BS(0, kk, nc + 3) = tf32r(vb[i].w);
    }
    __syncthreads();

    const int nslabs = K >> 5;
    for (int s = 0; s < nslabs; ++s) {
        const int cur = s & 1, nxt = cur ^ 1;
        const bool more = (s + 1 < nslabs);
        if (more) {
            int kn = (s + 1) * 32;
#pragma unroll
            for (int i = 0; i < 4; ++i) {
                int f4 = tid + i * 256;
                int r = f4 >> 3, kc = (f4 & 7) * 4;
                va[i] = *(const float4*)&A[(size_t)(row0 + r) * K + kn + kc];
                int kk = f4 >> 5, nc = (f4 & 31) * 4;
                vb[i] = *(const float4*)&Bm[(size_t)(kn + kk) * N + col0 + nc];
            }
        }
#pragma unroll
        for (int ks = 0; ks < 4; ++ks) {
            const int kb = ks * 8;
            unsigned a[2][4];
#pragma unroll
            for (int mt = 0; mt < 2; ++mt) {
                int rb = wm * 32 + mt * 16;
                a[mt][0] = __float_as_uint(TG_AS(cur, rb + g, kb + t));
                a[mt][1] = __float_as_uint(TG_AS(cur, rb + g + 8, kb + t));
                a[mt][2] = __float_as_uint(TG_AS(cur, rb + g, kb + t + 4));
                a[mt][3] = __float_as_uint(TG_AS(cur, rb + g + 8, kb + t + 4));
            }
#pragma unroll
            for (int nt = 0; nt < 8; ++nt) {
                int nb = wn * 64 + nt * 8;
                unsigned b0 = __float_as_uint(TG_BS(cur, kb + t, nb + g));
                unsigned b1 = __float_as_uint(TG_BS(cur, kb + t + 4, nb + g));
#pragma unroll
                for (int mt = 0; mt < 2; ++mt)
                    mma8(acc[mt][nt], a[mt][0], a[mt][1], a[mt][2], a[mt][3], b0, b1);
            }
        }
        if (more) {
#pragma unroll
            for (int i = 0; i < 4; ++i) {
                int f4 = tid + i * 256;
                int r = f4 >> 3, kc = (f4 & 7) * 4;
                TG_AS(nxt, r, kc + 0) = tf32r(va[i].x);
                TG_AS(nxt, r, kc + 1) = tf32r(va[i].y);
                TG_AS(nxt, r, kc + 2) = tf32r(va[i].z);
                TG_AS(nxt, r, kc + 3) = tf32r(va[i].w);
                int kk = f4 >> 5, nc = (f4 & 31) * 4;
                TG_BS(nxt, kk, nc + 0) = tf32r(vb[i].x);
                TG_BS(nxt, kk, nc + 1) = tf32r(vb[i].y);
                TG_BS(nxt, kk, nc + 2) = tf32r(vb[i].z);
                TG_BS(nxt, kk, nc + 3) = tf32r(vb[i].w);
            }
            __syncthreads();
        }
    }
#pragma unroll
    for (int mt = 0; mt < 2; ++mt) {
#pragma unroll
        for (int nt = 0; nt < 8; ++nt) {
            int r = row0 + wm * 32 + mt * 16 + g;
            int c = col0 + wn * 64 + nt * 8 + 2 * t;
            *(float2*)&C[(size_t)r * N + c] = make_float2(acc[mt][nt][0], acc[mt][nt][1]);
            *(float2*)&C[(size_t)(r + 8) * N + c] = make_float2(acc[mt][nt][2], acc[mt][nt][3]);
        }
    }
}

// ------- out-proj: out[r][c] = (P0[r]+P1[r]) . w_out[:,c] + b[c] --------------
// 8 rows per block (128 blocks): B-matrix L2 traffic cut 4x vs 2-row version.
__global__ void __launch_bounds__(256) outproj_kernel(
    const float* __restrict__ A0, const float* __restrict__ A1,
    const float* __restrict__ B,
    const float* __restrict__ bias, float* __restrict__ C)
{
    __shared__ float As[8][512];
    const int tid = threadIdx.x;
    const int r0 = blockIdx.x * 8;
#pragma unroll
    for (int i = 0; i < 4; ++i) {
        int e = tid + i * 256;   // 1024 float4 = 8 rows x 512
        float4 a = ((const float4*)&A0[(size_t)r0 * 512])[e];
        float4 b = ((const float4*)&A1[(size_t)r0 * 512])[e];
        a.x += b.x; a.y += b.y; a.z += b.z; a.w += b.w;
        ((float4*)&As[0][0])[e] = a;
    }
    __syncthreads();
    const int c = tid & 127, grp = tid >> 7;  // grp 0: rows 0-3, grp 1: rows 4-7
    float acc0 = bias[c], acc1 = acc0, acc2 = acc0, acc3 = acc0;
    const float* bp = B + c;
    const float* a0r = As[grp * 4 + 0];
    const float* a1r = As[grp * 4 + 1];
    const float* a2r = As[grp * 4 + 2];
    const float* a3r = As[grp * 4 + 3];
#pragma unroll 4
    for (int k = 0; k < 512; k += 4) {
        float b0 = bp[(size_t)(k + 0) * 128];
        float b1 = bp[(size_t)(k + 1) * 128];
        float b2 = bp[(size_t)(k + 2) * 128];
        float b3 = bp[(size_t)(k + 3) * 128];
        float4 x0 = *(const float4*)&a0r[k];
        float4 x1 = *(const float4*)&a1r[k];
        float4 x2 = *(const float4*)&a2r[k];
        float4 x3 = *(const float4*)&a3r[k];
        acc0 += x0.x * b0 + x0.y * b1 + x0.z * b2 + x0.w * b3;
        acc1 += x1.x * b0 + x1.y * b1 + x1.z * b2 + x1.w * b3;
        acc2 += x2.x * b0 + x2.y * b1 + x2.z * b2 + x2.w * b3;
        acc3 += x3.x * b0 + x3.y * b1 + x3.z * b2 + x3.w * b3;
    }
    int rb = r0 + grp * 4;
    C[(size_t)(rb + 0) * 128 + c] = acc0;
    C[(size_t)(rb + 1) * 128 + c] = acc1;
    C[(size_t)(rb + 2) * 128 + c] = acc2;
    C[(size_t)(rb + 3) * 128 + c] = acc3;
}

// ---------------- sim via tf32 mma: per (p-half, h, b) 64x256x32 --------------
__global__ void __launch_bounds__(256) sim_mma_kernel()
{
    __shared__ float As[64 * 34];   // [l][d]
    __shared__ float Bs[32 * 258];  // [d][p] (transposed)
    const int ph = blockIdx.x, h = blockIdx.y, b = blockIdx.z;
    const int tid = threadIdx.x;
    const int w = tid >> 5, lane = tid & 31, g = lane >> 2, t = lane & 3;

    for (int e = tid; e < 2048; e += 256) {
        int lr = e >> 5, d = e & 31;
        As[lr * 34 + d] = tf32r(g_qk[((size_t)(b * 64 + lr)) * 512 + h * 32 + d]);
    }
    for (int e = tid; e < 8192; e += 256) {
        int p = e >> 5, d = e & 31;
        Bs[d * 258 + p] = tf32r(g_cqk[((size_t)(b * 512 + ph * 256 + p)) * 512 + h * 32 + d]);
    }
    __syncthreads();

    float acc[4][4][4];
#pragma unroll
    for (int mi = 0; mi < 4; ++mi)
#pragma unroll
        for (int nt = 0; nt < 4; ++nt)
#pragma unroll
            for (int q = 0; q < 4; ++q) acc[mi][nt][q] = 0.f;

    const int n0 = w * 32;
#pragma unroll
    for (int kt = 0; kt < 4; ++kt) {
        const int kb = kt * 8;
        unsigned aF[4][4];
#pragma unroll
        for (int mi = 0; mi < 4; ++mi) {
            int rA = mi * 16;
            aF[mi][0] = __float_as_uint(As[(rA + g) * 34 + kb + t]);
            aF[mi][1] = __float_as_uint(As[(rA + g + 8) * 34 + kb + t]);
            aF[mi][2] = __float_as_uint(As[(rA + g) * 34 + kb + t + 4]);
            aF[mi][3] = __float_as_uint(As[(rA + g + 8) * 34 + kb + t + 4]);
        }
#pragma unroll
        for (int nt = 0; nt < 4; ++nt) {
            int nb = n0 + nt * 8;
            unsigned b0 = __float_as_uint(Bs[(kb + t) * 258 + nb + g]);
            unsigned b1 = __float_as_uint(Bs[(kb + t + 4) * 258 + nb + g]);
#pragma unroll
            for (int mi = 0; mi < 4; ++mi)
                mma8(acc[mi][nt], aF[mi][0], aF[mi][1], aF[mi][2], aF[mi][3], b0, b1);
        }
    }
    const float SCALE = 0.17677669529663687f; // 32^-0.5
#pragma unroll
    for (int mi = 0; mi < 4; ++mi)
#pragma unroll
        for (int nt = 0; nt < 4; ++nt) {
            int lr = mi * 16 + g;
            int pc = ph * 256 + n0 + nt * 8 + 2 * t;
            size_t base = (((size_t)(b * 16 + h)) * 64 + lr) * 512 + pc;
            *(float2*)&g_sim[base] =
                make_float2(acc[mi][nt][0] * SCALE, acc[mi][nt][1] * SCALE);
            *(float2*)&g_sim[base + (size_t)8 * 512] =
                make_float2(acc[mi][nt][2] * SCALE, acc[mi][nt][3] * SCALE);
        }
}

// ------- fused pairwise MLPs + softmax + distance path (FFMA2, 2 p/thread) ----
#define SM4_FLOATS (512 * 33 + 2048 + 2048 + 256 + 1024 + 64 + 16 + 32 + 1536 + 48 + 96)
__global__ void __launch_bounds__(256) pair_kernel(
    const float* __restrict__ xp, const float* __restrict__ xl,
    const float* __restrict__ w_mlp1, const float* __restrict__ w_mlp2,
    const float* __restrict__ b_mlp2, const float* __restrict__ sigma,
    const float* __restrict__ w_pe1, const float* __restrict__ b_pe1,
    const float* __restrict__ w_pe2, const float* __restrict__ b_pe2,
    const float* __restrict__ w_dis1, const float* __restrict__ b_dis1,
    const float* __restrict__ w_dis2, const float* __restrict__ b_dis2,
    float* __restrict__ out)
{
    extern __shared__ float sm[];
    float* lg    = sm;                 // 512*33 logits -> probs(c>=16)
    float* w1t   = lg + 512 * 33;      // [k][i] transposed w_mlp1, 64*32
    float* w2s   = w1t + 2048;         // w_mlp2 as-is, 64*32
    float* wpe1t = w2s + 2048;         // [k][i(pad4)], 64*4
    float* wpe2s = wpe1t + 256;        // w_pe2 as-is, 64*16
    float* bpe1s = wpe2s + 1024;       // 64
    float* bpe2s = bpe1s + 64;         // 16
    float* bm2s  = bpe2s + 16;         // 32
    float* xps   = bm2s + 32;          // [512][3] raw protein coords
    float* ods   = xps + 1536;         // [3][16]
    float* zs    = ods + 48;           // [3][32]

    const int tid = threadIdx.x;
    const int l = blockIdx.x, b = blockIdx.y;

    for (int e = tid; e < 2048; e += 256) { int i = e >> 6, k = e & 63; w1t[k * 32 + i] = w_mlp1[e]; }
    for (int e = tid; e < 2048; e += 256) w2s[e] = w_mlp2[e];
    if (tid < 192) { int i = tid >> 6, k = tid & 63; wpe1t[k * 4 + i] = w_pe1[tid]; }
    for (int e = tid; e < 1024; e += 256) wpe2s[e] = w_pe2[e];
    if (tid < 64) bpe1s[tid] = b_pe1[tid];
    if (tid < 16) bpe2s[tid] = b_pe2[tid];
    if (tid < 32) bm2s[tid]  = b_mlp2[tid];
    __syncthreads();

    const float sg = sigma[0];
    const float cpe = -0.5f / (sg * sg);
    const int rowl = b * 64 + l;
    const float xl0 = xl[rowl * 3 + 0], xl1 = xl[rowl * 3 + 1], xl2 = xl[rowl * 3 + 2];

    const int p0 = tid, p1 = tid + 256;

    // s pairs for both p: [0..7] sim heads, [8..15] dis_emb
    u64 sp0[16], sp1[16];
    {
        size_t base = (((size_t)b * 16) * 64 + l) * 512;
#pragma unroll
        for (int h2 = 0; h2 < 8; ++h2) {
            size_t o0 = base + (size_t)(2 * h2) * 64 * 512;
            size_t o1 = base + (size_t)(2 * h2 + 1) * 64 * 512;
            sp0[h2] = pk2(g_sim[o0 + p0], g_sim[o1 + p0]);
            sp1[h2] = pk2(g_sim[o0 + p1], g_sim[o1 + p1]);
        }
    }

    // positional-encoding MLP: 3 -> 64 (mish) -> 16, both p share weight loads
    {
        const float* xpr0 = xp + (size_t)(b * 512 + p0) * 3;
        const float* xpr1 = xp + (size_t)(b * 512 + p1) * 3;
        float xA0 = xpr0[0], xA1 = xpr0[1], xA2 = xpr0[2];
        float xB0 = xpr1[0], xB1 = xpr1[1], xB2 = xpr1[2];
        xps[p0 * 3 + 0] = xA0; xps[p0 * 3 + 1] = xA1; xps[p0 * 3 + 2] = xA2;
        xps[p1 * 3 + 0] = xB0; xps[p1 * 3 + 1] = xB1; xps[p1 * 3 + 2] = xB2;

        float peA0 = __expf(cpe * (xA0 - xl0));
        float peA1 = __expf(cpe * (xA1 - xl1));
        float peA2 = __expf(cpe * (xA2 - xl2));
        float peB0 = __expf(cpe * (xB0 - xl0));
        float peB1 = __expf(cpe * (xB1 - xl1));
        float peB2 = __expf(cpe * (xB2 - xl2));

        u64 deA[8], deB[8];
#pragma unroll
        for (int j = 0; j < 8; ++j) {
            u64 bb = pk2(bpe2s[2 * j], bpe2s[2 * j + 1]);
            deA[j] = bb; deB[j] = bb;
        }
#pragma unroll 2
        for (int k = 0; k < 64; ++k) {
            float w0 = wpe1t[k * 4], w1 = wpe1t[k * 4 + 1], w2 = wpe1t[k * 4 + 2];
            float bk = bpe1s[k];
            float hA = bk + peA0 * w0 + peA1 * w1 + peA2 * w2;
            float hB = bk + peB0 * w0 + peB1 * w1 + peB2 * w2;
            float mA = mishf(hA), mB = mishf(hB);
            u64 mA2 = pk2(mA, mA), mB2 = pk2(mB, mB);
            const ulonglong2* wr = (const ulonglong2*)(wpe2s + k * 16);
#pragma unroll
            for (int q = 0; q < 4; ++q) {
                ulonglong2 w = wr[q];
                deA[2 * q + 0] = ffma2(mA2, w.x, deA[2 * q + 0]);
                deA[2 * q + 1] = ffma2(mA2, w.y, deA[2 * q + 1]);
                deB[2 * q + 0] = ffma2(mB2, w.x, deB[2 * q + 0]);
                deB[2 * q + 1] = ffma2(mB2, w.y, deB[2 * q + 1]);
            }
        }
#pragma unroll
        for (int j = 0; j < 8; ++j) { sp0[8 + j] = deA[j]; sp1[8 + j] = deB[j]; }
    }

    // attention MLP: 32 -> 64 (mish) -> 32, single pass, split h-chains for ILP
    const u64 z2 = pk2(0.f, 0.f);
    u64 oA[16], oB[16];
#pragma unroll
    for (int j = 0; j < 16; ++j) {
        u64 bb = pk2(bm2s[2 * j], bm2s[2 * j + 1]);
        oA[j] = bb; oB[j] = bb;
    }
#pragma unroll 2
    for (int k = 0; k < 64; ++k) {
        const ulonglong2* w1r = (const ulonglong2*)(w1t + k * 32);
        u64 hA0 = z2, hA1 = z2, hB0 = z2, hB1 = z2;
#pragma unroll
        for (int q = 0; q < 4; ++q) {
            ulonglong2 w = w1r[q];
            hA0 = ffma2(sp0[2 * q + 0], w.x, hA0);
            hA0 = ffma2(sp0[2 * q + 1], w.y, hA0);
            hB0 = ffma2(sp1[2 * q + 0], w.x, hB0);
            hB0 = ffma2(sp1[2 * q + 1], w.y, hB0);
        }
#pragma unroll
        for (int q = 4; q < 8; ++q) {
            ulonglong2 w = w1r[q];
            hA1 = ffma2(sp0[2 * q + 0], w.x, hA1);
            hA1 = ffma2(sp0[2 * q + 1], w.y, hA1);
            hB1 = ffma2(sp1[2 * q + 0], w.x, hB1);
            hB1 = ffma2(sp1[2 * q + 1], w.y, hB1);
        }
        float2 a0 = up2(hA0), a1 = up2(hA1);
        float2 b0 = up2(hB0), b1 = up2(hB1);
        float mA = mishf((a0.x + a0.y) + (a1.x + a1.y));
        float mB = mishf((b0.x + b0.y) + (b1.x + b1.y));
        u64 mA2 = pk2(mA, mA), mB2 = pk2(mB, mB);
        const ulonglong2* w2r = (const ulonglong2*)(w2s + k * 32);
#pragma unroll
        for (int q = 0; q < 8; ++q) {
            ulonglong2 w = w2r[q];
            oA[2 * q + 0] = ffma2(mA2, w.x, oA[2 * q + 0]);
            oA[2 * q + 1] = ffma2(mA2, w.y, oA[2 * q + 1]);
            oB[2 * q + 0] = ffma2(mB2, w.x, oB[2 * q + 0]);
            oB[2 * q + 1] = ffma2(mB2, w.y, oB[2 * q + 1]);
        }
    }
#pragma unroll
    for (int j = 0; j < 16; ++j) {
        float2 vA = up2(oA[j]);
        float2 vB = up2(oB[j]);
        lg[p0 * 33 + 2 * j + 0] = vA.x;
        lg[p0 * 33 + 2 * j + 1] = vA.y;
        lg[p1 * 33 + 2 * j + 0] = vB.x;
        lg[p1 * 33 + 2 * j + 1] = vB.y;
    }
    __syncthreads();

    // softmax: warp w owns channels 4w..4w+3; c<16 -> g_probs, c>=16 -> lg smem
    const int w = tid >> 5, lane = tid & 31;
#pragma unroll
    for (int cc = 0; cc < 4; ++cc) {
        int c = w * 4 + cc;
        float mx = -3.4e38f;
#pragma unroll
        for (int i = 0; i < 16; ++i) mx = fmaxf(mx, lg[(lane + i * 32) * 33 + c]);
#pragma unroll
        for (int off = 16; off; off >>= 1) mx = fmaxf(mx, __shfl_xor_sync(0xffffffffu, mx, off));
        float ev[16]; float sum = 0.f;
#pragma unroll
        for (int i = 0; i < 16; ++i) {
            ev[i] = __expf(lg[(lane + i * 32) * 33 + c] - mx);
            sum += ev[i];
        }
#pragma unroll
        for (int off = 16; off; off >>= 1) sum += __shfl_xor_sync(0xffffffffu, sum, off);
        float inv = 1.0f / sum;
        if (c < 16) {
            size_t base = (((size_t)b * 32 + c) * 64 + l) * 512;
#pragma unroll
            for (int i = 0; i < 16; ++i) g_probs[base + lane + i * 32] = ev[i] * inv;
        } else {
#pragma unroll
            for (int i = 0; i < 16; ++i) lg[(lane + i * 32) * 33 + c] = ev[i] * inv;
        }
    }
    __syncthreads();

    // ---- fused distance path: Σ_p prob·xp − xl, then tiny MLP into d_out ----
#pragma unroll
    for (int q = 0; q < 6; ++q) {
        int idx = w * 6 + q;
        int i = idx >> 4, h = idx & 15;
        float sum = 0.f;
#pragma unroll
        for (int it = 0; it < 16; ++it) {
            int p = lane + it * 32;
            sum += lg[p * 33 + 16 + h] * xps[p * 3 + i];
        }
#pragma unroll
        for (int off = 16; off; off >>= 1) sum += __shfl_xor_sync(0xffffffffu, sum, off);
        if (lane == 0) {
            float xli = (i == 0) ? xl0 : ((i == 1) ? xl1 : xl2);
            ods[i * 16 + h] = sum - xli;
        }
    }
    __syncthreads();
    if (tid < 96) {
        int i = tid >> 5, k = tid & 31;
        float hz = b_dis1[k];
#pragma unroll
        for (int j = 0; j < 16; ++j) hz += ods[i * 16 + j] * w_dis1[j * 32 + k];
        zs[i * 32 + k] = mishf(hz);
    }
    __syncthreads();
    if (tid < 48) {
        int i = tid / 16, h = tid % 16;
        float y = b_dis2[h];
#pragma unroll
        for (int k = 0; k < 32; ++k) y += zs[i * 32 + k] * w_dis2[k * 16 + h];
        out[OUT0 + (((size_t)b * 64 + l) * 3 + i) * 16 + h] = y;
    }
}

// ---- outagg via tf32 mma, k-split x2 + register-prefetch pipeline ------------
__global__ void __launch_bounds__(256) outagg_mma_kernel()
{
    __shared__ float As[64][68];
    __shared__ float Bs[64][40];
    const int b = blockIdx.x, h = blockIdx.y, z = blockIdx.z;
    const int tid = threadIdx.x;
    const int w = tid >> 5, lane = tid & 31, g = lane >> 2, t = lane & 3;
    const int mi = w >> 1, ni = w & 1;
    const int pbase = z * 256;
    float* outp = z ? g_outpre2 : g_outpre;

    float acc[2][4];
#pragma unroll
    for (int nt = 0; nt < 2; ++nt)
#pragma unroll
        for (int q = 0; q < 4; ++q) acc[nt][q] = 0.f;

    float4 pa[4], pb[2];
#pragma unroll
    for (int i = 0; i < 4; ++i) {
        int e = tid + i * 256;
        int lr = e >> 4, p4 = (e & 15) * 4;
        pa[i] = *(const float4*)&g_probs[(((size_t)b * 32 + h) * 64 + lr) * 512 + pbase + p4];
    }
#pragma unroll
    for (int i = 0; i < 2; ++i) {
        int e = tid + i * 256;
        int p = e >> 3, d4 = (e & 7) * 4;
        pb[i] = *(const float4*)&g_cv[((size_t)(b * 512 + pbase + p)) * 512 + h * 32 + d4];
    }

    for (int c4 = 0; c4 < 4; ++c4) {
        __syncthreads();
#pragma unroll
        for (int i = 0; i < 4; ++i) {
            int e = tid + i * 256;
            int lr = e >> 4, p4 = (e & 15) * 4;
            As[lr][p4 + 0] = tf32r(pa[i].x);
            As[lr][p4 + 1] = tf32r(pa[i].y);
            As[lr][p4 + 2] = tf32r(pa[i].z);
            As[lr][p4 + 3] = tf32r(pa[i].w);
        }
#pragma unroll
        for (int i = 0; i < 2; ++i) {
            int e = tid + i * 256;
            int p = e >> 3, d4 = (e & 7) * 4;
            Bs[p][d4 + 0] = tf32r(pb[i].x);
            Bs[p][d4 + 1] = tf32r(pb[i].y);
            Bs[p][d4 + 2] = tf32r(pb[i].z);
            Bs[p][d4 + 3] = tf32r(pb[i].w);
        }
        __syncthreads();
        if (c4 < 3) {
            int pc = pbase + (c4 + 1) * 64;
#pragma unroll
            for (int i = 0; i < 4; ++i) {
                int e = tid + i * 256;
                int lr = e >> 4, p4 = (e & 15) * 4;
                pa[i] = *(const float4*)&g_probs[(((size_t)b * 32 + h) * 64 + lr) * 512 + pc + p4];
            }
#pragma unroll
            for (int i = 0; i < 2; ++i) {
                int e = tid + i * 256;
                int p = e >> 3, d4 = (e & 7) * 4;
                pb[i] = *(const float4*)&g_cv[((size_t)(b * 512 + pc + p)) * 512 + h * 32 + d4];
            }
        }
#pragma unroll
        for (int kt = 0; kt < 8; ++kt) {
            const int kb = kt * 8;
            int rA = mi * 16;
            unsigned a0 = __float_as_uint(As[rA + g][kb + t]);
            unsigned a1 = __float_as_uint(As[rA + g + 8][kb + t]);
            unsigned a2 = __float_as_uint(As[rA + g][kb + t + 4]);
            unsigned a3 = __float_as_uint(As[rA + g + 8][kb + t + 4]);
#pragma unroll
            for (int nt = 0; nt < 2; ++nt) {
                int nb = ni * 16 + nt * 8;
                unsigned b0 = __float_as_uint(Bs[kb + t][nb + g]);
                unsigned b1 = __float_as_uint(Bs[kb + t + 4][nb + g]);
                mma8(acc[nt], a0, a1, a2, a3, b0, b1);
            }
        }
    }
#pragma unroll
    for (int nt = 0; nt < 2; ++nt) {
        int r = mi * 16 + g;
        int c = ni * 16 + nt * 8 + 2 * t;
        size_t base = ((size_t)(b * 64 + r)) * 512 + h * 32 + c;
        *(float2*)&outp[base] = make_float2(acc[nt][0], acc[nt][1]);
        *(float2*)&outp[base + (size_t)8 * 512] = make_float2(acc[nt][2], acc[nt][3]);
    }
}

// ---------------- launch -------------------------------------------------------
extern "C" void kernel_launch(void* const* d_in, const int* in_sizes, int n_in,
                              void* d_out, int out_size)
{
    (void)in_sizes; (void)n_in; (void)out_size;
    const float* h_ligand = (const float*)d_in[0];
    const float* context  = (const float*)d_in[1];
    const float* xp       = (const float*)d_in[2];
    const float* xl       = (const float*)d_in[3];
    const float* w_qk     = (const float*)d_in[4];
    // d_in[5] = w_v (unused by the reference)
    const float* w_cqk    = (const float*)d_in[6];
    const float* w_cv     = (const float*)d_in[7];
    const float* w_mlp1   = (const float*)d_in[8];
    const float* w_mlp2   = (const float*)d_in[9];
    const float* b_mlp2   = (const float*)d_in[10];
    const float* w_out    = (const float*)d_in[11];
    const float* b_out    = (const float*)d_in[12];
    const float* w_dis1   = (const float*)d_in[13];
    const float* b_dis1   = (const float*)d_in[14];
    const float* w_dis2   = (const float*)d_in[15];
    const float* b_dis2   = (const float*)d_in[16];
    const float* sigma    = (const float*)d_in[17];
    const float* w_pe1    = (const float*)d_in[18];
    const float* b_pe1    = (const float*)d_in[19];
    const float* w_pe2    = (const float*)d_in[20];
    const float* b_pe2    = (const float*)d_in[21];
    float* out = (float*)d_out;

    void *p_qk, *p_cqk, *p_cv, *p_outpre, *p_outpre2;
    cudaGetSymbolAddress(&p_qk, g_qk);
    cudaGetSymbolAddress(&p_cqk, g_cqk);
    cudaGetSymbolAddress(&p_cv, g_cv);
    cudaGetSymbolAddress(&p_outpre, g_outpre);
    cudaGetSymbolAddress(&p_outpre2, g_outpre2);

    // #1 all three projections in ONE launch (544 blocks, double-buffered)
    cudaFuncSetAttribute(tgemm_all, cudaFuncAttributeMaxDynamicSharedMemorySize,
                         TG_SM_BYTES);
    tgemm_all<<<544, 256, TG_SM_BYTES>>>(context, h_ligand, w_cqk, w_cv, w_qk,
                                         (float*)p_cqk, (float*)p_cv, (float*)p_qk);
    // #2 similarity scores (tf32 mma)
    sim_mma_kernel<<<dim3(2, 16, 16), 256>>>();

    // #3 fused pairwise MLPs + softmax + distance path (banked R7 config)
    const int sm4_bytes = SM4_FLOATS * (int)sizeof(float);
    cudaFuncSetAttribute(pair_kernel, cudaFuncAttributeMaxDynamicSharedMemorySize, sm4_bytes);
    pair_kernel<<<dim3(64, 16), 256, sm4_bytes>>>(
        xp, xl, w_mlp1, w_mlp2, b_mlp2, sigma, w_pe1, b_pe1, w_pe2, b_pe2,
        w_dis1, b_dis1, w_dis2, b_dis2, out);

    // #4 context path: attn @ cv (tf32 mma, k-split x2, pipelined)
    outagg_mma_kernel<<<dim3(16, 16, 2), 256>>>();
    // #5 out-proj (+bias, sums 2 partials) into d_out — 128 blocks x 8 rows
    outproj_kernel<<<128, 256>>>((const float*)p_outpre, (const float*)p_outpre2,
                                 w_out, b_out, out);
}

// round 13
// speedup vs baseline: 1.0199x; 1.0199x over previous
#include <cuda_runtime.h>
#include <cstddef>

#define OUT0 131072 // 1024*128, offset of out_dis in d_out

typedef unsigned long long u64;

// ---------------- scratch (device globals; no allocation allowed) -------------
__device__ float g_qk[1024 * 512];            // [B*L][INNER]
__device__ float g_cqk[8192 * 512];           // [B*P][INNER]
__device__ float g_cv[8192 * 512];            // [B*P][INNER]
__device__ float g_sim[16 * 16 * 64 * 512];   // [b][h][l][p] (scaled)
__device__ float g_probs[16 * 32 * 64 * 512]; // [b][c][l][p] (only c<16 written)
__device__ float g_outpre[1024 * 512];        // partial 0 (p 0..255)
__device__ float g_outpre2[1024 * 512];       // partial 1 (p 256..511)

// mish(x) = x*tanh(softplus(x)) = x * u/(u+2), u = e^x*(e^x+2)  (exact identity)
__device__ __forceinline__ float mishf(float x) {
    float t = __expf(fminf(x, 8.0f));
    float u = t * (t + 2.0f);
    return x * __fdividef(u, u + 2.0f);
}

__device__ __forceinline__ float tf32r(float x) {
    unsigned u;
    asm("cvt.rna.tf32.f32 %0, %1;" : "=r"(u) : "f"(x));
    return __uint_as_float(u);
}

__device__ __forceinline__ void mma8(float* c, unsigned a0, unsigned a1,
                                     unsigned a2, unsigned a3,
                                     unsigned b0, unsigned b1) {
    asm volatile(
        "mma.sync.aligned.m16n8k8.row.col.f32.tf32.tf32.f32 "
        "{%0,%1,%2,%3},{%4,%5,%6,%7},{%8,%9},{%0,%1,%2,%3};"
        : "+f"(c[0]), "+f"(c[1]), "+f"(c[2]), "+f"(c[3])
        : "r"(a0), "r"(a1), "r"(a2), "r"(a3), "r"(b0), "r"(b1));
}

// ---- packed f32x2 helpers (Blackwell FFMA2 — only reachable via PTX) ---------
__device__ __forceinline__ u64 ffma2(u64 a, u64 b, u64 c) {
    u64 d;
    asm("fma.rn.f32x2 %0, %1, %2, %3;" : "=l"(d) : "l"(a), "l"(b), "l"(c));
    return d;
}
__device__ __forceinline__ u64 pk2(float x, float y) {
    u64 r;
    asm("mov.b64 %0, {%1, %2};" : "=l"(r) : "f"(x), "f"(y));
    return r;
}
__device__ __forceinline__ float2 up2(u64 v) {
    float2 r;
    asm("mov.b64 {%0, %1}, %2;" : "=f"(r.x), "=f"(r.y) : "l"(v));
    return r;
}

// ------ unified tf32 GEMM launch: blocks 0..511 cqk|cv (K=256), 512..543 qk ----
// Software-pipelined: next k-slab's global loads issued before the mma phase.
__global__ void __launch_bounds__(256) tgemm_all(
    const float* __restrict__ ctx, const float* __restrict__ hlig,
    const float* __restrict__ w_cqk, const float* __restrict__ w_cv,
    const float* __restrict__ w_qk,
    float* __restrict__ cqk, float* __restrict__ cv, float* __restrict__ qk)
{
    __shared__ float As[128][36];
    __shared__ float Bs[32][136];
    const int tid = threadIdx.x;
    const int lane = tid & 31, warp = tid >> 5;
    const int wm = warp >> 1, wn = warp & 1;
    const int g = lane >> 2, t = lane & 3;
    const int N = 512;

    int bid = blockIdx.x;
    const float* A; const float* Bm; float* C;
    int row0, col0, K;
    if (bid < 512) {
        row0 = (bid >> 3) * 128; col0 = (bid & 7) * 128;
        A = ctx; K = 256;
        if (col0 >= 512) { Bm = w_cv; C = cv; col0 -= 512; }
        else             { Bm = w_cqk; C = cqk; }
    } else {
        int b2 = bid - 512;
        row0 = (b2 >> 2) * 128; col0 = (b2 & 3) * 128;
        A = hlig; Bm = w_qk; C = qk; K = 128;
    }

    float acc[2][8][4];
#pragma unroll
    for (int mt = 0; mt < 2; ++mt)
#pragma unroll
        for (int nt = 0; nt < 8; ++nt)
#pragma unroll
            for (int q = 0; q < 4; ++q) acc[mt][nt][q] = 0.f;

    float4 va[4], vb[4];
    // prologue: load slab 0
#pragma unroll
    for (int i = 0; i < 4; ++i) {
        int f4 = tid + i * 256;
        int r = f4 >> 3, kc = (f4 & 7) * 4;
        va[i] = *(const float4*)&A[(size_t)(row0 + r) * K + kc];
        int kk = f4 >> 5, nc = (f4 & 31) * 4;
        vb[i] = *(const float4*)&Bm[(size_t)kk * N + col0 + nc];
    }

    for (int k0 = 0; k0 < K; k0 += 32) {
        __syncthreads();
#pragma unroll
        for (int i = 0; i < 4; ++i) {
            int f4 = tid + i * 256;
            int r = f4 >> 3, kc = (f4 & 7) * 4;
            As[r][kc + 0] = tf32r(va[i].x);
            As[r][kc + 1] = tf32r(va[i].y);
            As[r][kc + 2] = tf32r(va[i].z);
            As[r][kc + 3] = tf32r(va[i].w);
            int kk = f4 >> 5, nc = (f4 & 31) * 4;
            Bs[kk][nc + 0] = tf32r(vb[i].x);
            Bs[kk][nc + 1] = tf32r(vb[i].y);
            Bs[kk][nc + 2] = tf32r(vb[i].z);
            Bs[kk][nc + 3] = tf32r(vb[i].w);
        }
        __syncthreads();
        // prefetch next slab while mma runs
        if (k0 + 32 < K) {
            int kn = k0 + 32;
#pragma unroll
            for (int i = 0; i < 4; ++i) {
                int f4 = tid + i * 256;
                int r = f4 >> 3, kc = (f4 & 7) * 4;
                va[i] = *(const float4*)&A[(size_t)(row0 + r) * K + kn + kc];
                int kk = f4 >> 5, nc = (f4 & 31) * 4;
                vb[i] = *(const float4*)&Bm[(size_t)(kn + kk) * N + col0 + nc];
            }
        }
#pragma unroll
        for (int ks = 0; ks < 4; ++ks) {
            const int kb = ks * 8;
            unsigned a[2][4];
#pragma unroll
            for (int mt = 0; mt < 2; ++mt) {
                int rb = wm * 32 + mt * 16;
                a[mt][0] = __float_as_uint(As[rb + g][kb + t]);
                a[mt][1] = __float_as_uint(As[rb + g + 8][kb + t]);
                a[mt][2] = __float_as_uint(As[rb + g][kb + t + 4]);
                a[mt][3] = __float_as_uint(As[rb + g + 8][kb + t + 4]);
            }
#pragma unroll
            for (int nt = 0; nt < 8; ++nt) {
                int nb = wn * 64 + nt * 8;
                unsigned b0 = __float_as_uint(Bs[kb + t][nb + g]);
                unsigned b1 = __float_as_uint(Bs[kb + t + 4][nb + g]);
#pragma unroll
                for (int mt = 0; mt < 2; ++mt)
                    mma8(acc[mt][nt], a[mt][0], a[mt][1], a[mt][2], a[mt][3], b0, b1);
            }
        }
    }
#pragma unroll
    for (int mt = 0; mt < 2; ++mt) {
#pragma unroll
        for (int nt = 0; nt < 8; ++nt) {
            int r = row0 + wm * 32 + mt * 16 + g;
            int c = col0 + wn * 64 + nt * 8 + 2 * t;
            *(float2*)&C[(size_t)r * N + c] = make_float2(acc[mt][nt][0], acc[mt][nt][1]);
            *(float2*)&C[(size_t)(r + 8) * N + c] = make_float2(acc[mt][nt][2], acc[mt][nt][3]);
        }
    }
}

// ------- out-proj: out[r][c] = (P0[r]+P1[r]) . w_out[:,c] + b[c] --------------
// 4 rows per block (256 blocks): halves w_out L2 traffic vs 2-row, keeps fill.
__global__ void __launch_bounds__(256) outproj_kernel(
    const float* __restrict__ A0, const float* __restrict__ A1,
    const float* __restrict__ B,
    const float* __restrict__ bias, float* __restrict__ C)
{
    __shared__ float As[4][512];
    const int tid = threadIdx.x;
    const int r0 = blockIdx.x * 4;
#pragma unroll
    for (int i = 0; i < 2; ++i) {
        int e = tid + i * 256;   // 512 float4 = 4 rows x 512
        float4 a = ((const float4*)&A0[(size_t)r0 * 512])[e];
        float4 b = ((const float4*)&A1[(size_t)r0 * 512])[e];
        a.x += b.x; a.y += b.y; a.z += b.z; a.w += b.w;
        ((float4*)&As[0][0])[e] = a;
    }
    __syncthreads();
    const int c = tid & 127, grp = tid >> 7;  // grp 0: rows 0-1, grp 1: rows 2-3
    float acc0 = bias[c], acc1 = acc0;
    const float* bp = B + c;
    const float* a0r = As[grp * 2 + 0];
    const float* a1r = As[grp * 2 + 1];
#pragma unroll 4
    for (int k = 0; k < 512; k += 4) {
        float b0 = bp[(size_t)(k + 0) * 128];
        float b1 = bp[(size_t)(k + 1) * 128];
        float b2 = bp[(size_t)(k + 2) * 128];
        float b3 = bp[(size_t)(k + 3) * 128];
        float4 x0 = *(const float4*)&a0r[k];
        float4 x1 = *(const float4*)&a1r[k];
        acc0 += x0.x * b0 + x0.y * b1 + x0.z * b2 + x0.w * b3;
        acc1 += x1.x * b0 + x1.y * b1 + x1.z * b2 + x1.w * b3;
    }
    int rb = r0 + grp * 2;
    C[(size_t)(rb + 0) * 128 + c] = acc0;
    C[(size_t)(rb + 1) * 128 + c] = acc1;
}

// ---------------- sim via tf32 mma: per (p-half, h, b) 64x256x32 --------------
__global__ void __launch_bounds__(256) sim_mma_kernel()
{
    __shared__ float As[64 * 34];   // [l][d]
    __shared__ float Bs[32 * 258];  // [d][p] (transposed)
    const int ph = blockIdx.x, h = blockIdx.y, b = blockIdx.z;
    const int tid = threadIdx.x;
    const int w = tid >> 5, lane = tid & 31, g = lane >> 2, t = lane & 3;

    for (int e = tid; e < 2048; e += 256) {
        int lr = e >> 5, d = e & 31;
        As[lr * 34 + d] = tf32r(g_qk[((size_t)(b * 64 + lr)) * 512 + h * 32 + d]);
    }
    for (int e = tid; e < 8192; e += 256) {
        int p = e >> 5, d = e & 31;
        Bs[d * 258 + p] = tf32r(g_cqk[((size_t)(b * 512 + ph * 256 + p)) * 512 + h * 32 + d]);
    }
    __syncthreads();

    float acc[4][4][4];
#pragma unroll
    for (int mi = 0; mi < 4; ++mi)
#pragma unroll
        for (int nt = 0; nt < 4; ++nt)
#pragma unroll
            for (int q = 0; q < 4; ++q) acc[mi][nt][q] = 0.f;

    const int n0 = w * 32;
#pragma unroll
    for (int kt = 0; kt < 4; ++kt) {
        const int kb = kt * 8;
        unsigned aF[4][4];
#pragma unroll
        for (int mi = 0; mi < 4; ++mi) {
            int rA = mi * 16;
            aF[mi][0] = __float_as_uint(As[(rA + g) * 34 + kb + t]);
            aF[mi][1] = __float_as_uint(As[(rA + g + 8) * 34 + kb + t]);
            aF[mi][2] = __float_as_uint(As[(rA + g) * 34 + kb + t + 4]);
            aF[mi][3] = __float_as_uint(As[(rA + g + 8) * 34 + kb + t + 4]);
        }
#pragma unroll
        for (int nt = 0; nt < 4; ++nt) {
            int nb = n0 + nt * 8;
            unsigned b0 = __float_as_uint(Bs[(kb + t) * 258 + nb + g]);
            unsigned b1 = __float_as_uint(Bs[(kb + t + 4) * 258 + nb + g]);
#pragma unroll
            for (int mi = 0; mi < 4; ++mi)
                mma8(acc[mi][nt], aF[mi][0], aF[mi][1], aF[mi][2], aF[mi][3], b0, b1);
        }
    }
    const float SCALE = 0.17677669529663687f; // 32^-0.5
#pragma unroll
    for (int mi = 0; mi < 4; ++mi)
#pragma unroll
        for (int nt = 0; nt < 4; ++nt) {
            int lr = mi * 16 + g;
            int pc = ph * 256 + n0 + nt * 8 + 2 * t;
            size_t base = (((size_t)(b * 16 + h)) * 64 + lr) * 512 + pc;
            *(float2*)&g_sim[base] =
                make_float2(acc[mi][nt][0] * SCALE, acc[mi][nt][1] * SCALE);
            *(float2*)&g_sim[base + (size_t)8 * 512] =
                make_float2(acc[mi][nt][2] * SCALE, acc[mi][nt][3] * SCALE);
        }
}

// ------- fused pairwise MLPs + softmax + distance path (FFMA2, 2 p/thread) ----
#define SM4_FLOATS (512 * 33 + 2048 + 2048 + 256 + 1024 + 64 + 16 + 32 + 1536 + 48 + 96)
__global__ void __launch_bounds__(256) pair_kernel(
    const float* __restrict__ xp, const float* __restrict__ xl,
    const float* __restrict__ w_mlp1, const float* __restrict__ w_mlp2,
    const float* __restrict__ b_mlp2, const float* __restrict__ sigma,
    const float* __restrict__ w_pe1, const float* __restrict__ b_pe1,
    const float* __restrict__ w_pe2, const float* __restrict__ b_pe2,
    const float* __restrict__ w_dis1, const float* __restrict__ b_dis1,
    const float* __restrict__ w_dis2, const float* __restrict__ b_dis2,
    float* __restrict__ out)
{
    extern __shared__ float sm[];
    float* lg    = sm;                 // 512*33 logits -> probs(c>=16)
    float* w1t   = lg + 512 * 33;      // [k][i] transposed w_mlp1, 64*32
    float* w2s   = w1t + 2048;         // w_mlp2 as-is, 64*32
    float* wpe1t = w2s + 2048;         // [k][i(pad4)], 64*4
    float* wpe2s = wpe1t + 256;        // w_pe2 as-is, 64*16
    float* bpe1s = wpe2s + 1024;       // 64
    float* bpe2s = bpe1s + 64;         // 16
    float* bm2s  = bpe2s + 16;         // 32
    float* xps   = bm2s + 32;          // [512][3] raw protein coords
    float* ods   = xps + 1536;         // [3][16]
    float* zs    = ods + 48;           // [3][32]

    const int tid = threadIdx.x;
    const int l = blockIdx.x, b = blockIdx.y;

    for (int e = tid; e < 2048; e += 256) { int i = e >> 6, k = e & 63; w1t[k * 32 + i] = w_mlp1[e]; }
    for (int e = tid; e < 2048; e += 256) w2s[e] = w_mlp2[e];
    if (tid < 192) { int i = tid >> 6, k = tid & 63; wpe1t[k * 4 + i] = w_pe1[tid]; }
    for (int e = tid; e < 1024; e += 256) wpe2s[e] = w_pe2[e];
    if (tid < 64) bpe1s[tid] = b_pe1[tid];
    if (tid < 16) bpe2s[tid] = b_pe2[tid];
    if (tid < 32) bm2s[tid]  = b_mlp2[tid];
    __syncthreads();

    const float sg = sigma[0];
    const float cpe = -0.5f / (sg * sg);
    const int rowl = b * 64 + l;
    const float xl0 = xl[rowl * 3 + 0], xl1 = xl[rowl * 3 + 1], xl2 = xl[rowl * 3 + 2];

    const int p0 = tid, p1 = tid + 256;

    // s pairs for both p: [0..7] sim heads, [8..15] dis_emb
    u64 sp0[16], sp1[16];
    {
        size_t base = (((size_t)b * 16) * 64 + l) * 512;
#pragma unroll
        for (int h2 = 0; h2 < 8; ++h2) {
            size_t o0 = base + (size_t)(2 * h2) * 64 * 512;
            size_t o1 = base + (size_t)(2 * h2 + 1) * 64 * 512;
            sp0[h2] = pk2(g_sim[o0 + p0], g_sim[o1 + p0]);
            sp1[h2] = pk2(g_sim[o0 + p1], g_sim[o1 + p1]);
        }
    }

    // positional-encoding MLP: 3 -> 64 (mish) -> 16, both p share weight loads
    {
        const float* xpr0 = xp + (size_t)(b * 512 + p0) * 3;
        const float* xpr1 = xp + (size_t)(b * 512 + p1) * 3;
        float xA0 = xpr0[0], xA1 = xpr0[1], xA2 = xpr0[2];
        float xB0 = xpr1[0], xB1 = xpr1[1], xB2 = xpr1[2];
        xps[p0 * 3 + 0] = xA0; xps[p0 * 3 + 1] = xA1; xps[p0 * 3 + 2] = xA2;
        xps[p1 * 3 + 0] = xB0; xps[p1 * 3 + 1] = xB1; xps[p1 * 3 + 2] = xB2;

        float peA0 = __expf(cpe * (xA0 - xl0));
        float peA1 = __expf(cpe * (xA1 - xl1));
        float peA2 = __expf(cpe * (xA2 - xl2));
        float peB0 = __expf(cpe * (xB0 - xl0));
        float peB1 = __expf(cpe * (xB1 - xl1));
        float peB2 = __expf(cpe * (xB2 - xl2));

        u64 deA[8], deB[8];
#pragma unroll
        for (int j = 0; j < 8; ++j) {
            u64 bb = pk2(bpe2s[2 * j], bpe2s[2 * j + 1]);
            deA[j] = bb; deB[j] = bb;
        }
#pragma unroll 2
        for (int k = 0; k < 64; ++k) {
            float w0 = wpe1t[k * 4], w1 = wpe1t[k * 4 + 1], w2 = wpe1t[k * 4 + 2];
            float bk = bpe1s[k];
            float hA = bk + peA0 * w0 + peA1 * w1 + peA2 * w2;
            float hB = bk + peB0 * w0 + peB1 * w1 + peB2 * w2;
            float mA = mishf(hA), mB = mishf(hB);
            u64 mA2 = pk2(mA, mA), mB2 = pk2(mB, mB);
            const ulonglong2* wr = (const ulonglong2*)(wpe2s + k * 16);
#pragma unroll
            for (int q = 0; q < 4; ++q) {
                ulonglong2 w = wr[q];
                deA[2 * q + 0] = ffma2(mA2, w.x, deA[2 * q + 0]);
                deA[2 * q + 1] = ffma2(mA2, w.y, deA[2 * q + 1]);
                deB[2 * q + 0] = ffma2(mB2, w.x, deB[2 * q + 0]);
                deB[2 * q + 1] = ffma2(mB2, w.y, deB[2 * q + 1]);
            }
        }
#pragma unroll
        for (int j = 0; j < 8; ++j) { sp0[8 + j] = deA[j]; sp1[8 + j] = deB[j]; }
    }

    // attention MLP: 32 -> 64 (mish) -> 32, single pass, split h-chains for ILP
    const u64 z2 = pk2(0.f, 0.f);
    u64 oA[16], oB[16];
#pragma unroll
    for (int j = 0; j < 16; ++j) {
        u64 bb = pk2(bm2s[2 * j], bm2s[2 * j + 1]);
        oA[j] = bb; oB[j] = bb;
    }
#pragma unroll 2
    for (int k = 0; k < 64; ++k) {
        const ulonglong2* w1r = (const ulonglong2*)(w1t + k * 32);
        u64 hA0 = z2, hA1 = z2, hB0 = z2, hB1 = z2;
#pragma unroll
        for (int q = 0; q < 4; ++q) {
            ulonglong2 w = w1r[q];
            hA0 = ffma2(sp0[2 * q + 0], w.x, hA0);
            hA0 = ffma2(sp0[2 * q + 1], w.y, hA0);
            hB0 = ffma2(sp1[2 * q + 0], w.x, hB0);
            hB0 = ffma2(sp1[2 * q + 1], w.y, hB0);
        }
#pragma unroll
        for (int q = 4; q < 8; ++q) {
            ulonglong2 w = w1r[q];
            hA1 = ffma2(sp0[2 * q + 0], w.x, hA1);
            hA1 = ffma2(sp0[2 * q + 1], w.y, hA1);
            hB1 = ffma2(sp1[2 * q + 0], w.x, hB1);
            hB1 = ffma2(sp1[2 * q + 1], w.y, hB1);
        }
        float2 a0 = up2(hA0), a1 = up2(hA1);
        float2 b0 = up2(hB0), b1 = up2(hB1);
        float mA = mishf((a0.x + a0.y) + (a1.x + a1.y));
        float mB = mishf((b0.x + b0.y) + (b1.x + b1.y));
        u64 mA2 = pk2(mA, mA), mB2 = pk2(mB, mB);
        const ulonglong2* w2r = (const ulonglong2*)(w2s + k * 32);
#pragma unroll
        for (int q = 0; q < 8; ++q) {
            ulonglong2 w = w2r[q];
            oA[2 * q + 0] = ffma2(mA2, w.x, oA[2 * q + 0]);
            oA[2 * q + 1] = ffma2(mA2, w.y, oA[2 * q + 1]);
            oB[2 * q + 0] = ffma2(mB2, w.x, oB[2 * q + 0]);
            oB[2 * q + 1] = ffma2(mB2, w.y, oB[2 * q + 1]);
        }
    }
#pragma unroll
    for (int j = 0; j < 16; ++j) {
        float2 vA = up2(oA[j]);
        float2 vB = up2(oB[j]);
        lg[p0 * 33 + 2 * j + 0] = vA.x;
        lg[p0 * 33 + 2 * j + 1] = vA.y;
        lg[p1 * 33 + 2 * j + 0] = vB.x;
        lg[p1 * 33 + 2 * j + 1] = vB.y;
    }
    __syncthreads();

    // softmax: warp w owns channels 4w..4w+3; c<16 -> g_probs, c>=16 -> lg smem
    const int w = tid >> 5, lane = tid & 31;
#pragma unroll
    for (int cc = 0; cc < 4; ++cc) {
        int c = w * 4 + cc;
        float mx = -3.4e38f;
#pragma unroll
        for (int i = 0; i < 16; ++i) mx = fmaxf(mx, lg[(lane + i * 32) * 33 + c]);
#pragma unroll
        for (int off = 16; off; off >>= 1) mx = fmaxf(mx, __shfl_xor_sync(0xffffffffu, mx, off));
        float ev[16]; float sum = 0.f;
#pragma unroll
        for (int i = 0; i < 16; ++i) {
            ev[i] = __expf(lg[(lane + i * 32) * 33 + c] - mx);
            sum += ev[i];
        }
#pragma unroll
        for (int off = 16; off; off >>= 1) sum += __shfl_xor_sync(0xffffffffu, sum, off);
        float inv = 1.0f / sum;
        if (c < 16) {
            size_t base = (((size_t)b * 32 + c) * 64 + l) * 512;
#pragma unroll
            for (int i = 0; i < 16; ++i) g_probs[base + lane + i * 32] = ev[i] * inv;
        } else {
#pragma unroll
            for (int i = 0; i < 16; ++i) lg[(lane + i * 32) * 33 + c] = ev[i] * inv;
        }
    }
    __syncthreads();

    // ---- fused distance path: Σ_p prob·xp − xl, then tiny MLP into d_out ----
#pragma unroll
    for (int q = 0; q < 6; ++q) {
        int idx = w * 6 + q;
        int i = idx >> 4, h = idx & 15;
        float sum = 0.f;
#pragma unroll
        for (int it = 0; it < 16; ++it) {
            int p = lane + it * 32;
            sum += lg[p * 33 + 16 + h] * xps[p * 3 + i];
        }
#pragma unroll
        for (int off = 16; off; off >>= 1) sum += __shfl_xor_sync(0xffffffffu, sum, off);
        if (lane == 0) {
            float xli = (i == 0) ? xl0 : ((i == 1) ? xl1 : xl2);
            ods[i * 16 + h] = sum - xli;
        }
    }
    __syncthreads();
    if (tid < 96) {
        int i = tid >> 5, k = tid & 31;
        float hz = b_dis1[k];
#pragma unroll
        for (int j = 0; j < 16; ++j) hz += ods[i * 16 + j] * w_dis1[j * 32 + k];
        zs[i * 32 + k] = mishf(hz);
    }
    __syncthreads();
    if (tid < 48) {
        int i = tid / 16, h = tid % 16;
        float y = b_dis2[h];
#pragma unroll
        for (int k = 0; k < 32; ++k) y += zs[i * 32 + k] * w_dis2[k * 16 + h];
        out[OUT0 + (((size_t)b * 64 + l) * 3 + i) * 16 + h] = y;
    }
}

// ---- outagg via tf32 mma, k-split x2 + register-prefetch pipeline ------------
__global__ void __launch_bounds__(256) outagg_mma_kernel()
{
    __shared__ float As[64][68];
    __shared__ float Bs[64][40];
    const int b = blockIdx.x, h = blockIdx.y, z = blockIdx.z;
    const int tid = threadIdx.x;
    const int w = tid >> 5, lane = tid & 31, g = lane >> 2, t = lane & 3;
    const int mi = w >> 1, ni = w & 1;
    const int pbase = z * 256;
    float* outp = z ? g_outpre2 : g_outpre;

    float acc[2][4];
#pragma unroll
    for (int nt = 0; nt < 2; ++nt)
#pragma unroll
        for (int q = 0; q < 4; ++q) acc[nt][q] = 0.f;

    float4 pa[4], pb[2];
#pragma unroll
    for (int i = 0; i < 4; ++i) {
        int e = tid + i * 256;
        int lr = e >> 4, p4 = (e & 15) * 4;
        pa[i] = *(const float4*)&g_probs[(((size_t)b * 32 + h) * 64 + lr) * 512 + pbase + p4];
    }
#pragma unroll
    for (int i = 0; i < 2; ++i) {
        int e = tid + i * 256;
        int p = e >> 3, d4 = (e & 7) * 4;
        pb[i] = *(const float4*)&g_cv[((size_t)(b * 512 + pbase + p)) * 512 + h * 32 + d4];
    }

    for (int c4 = 0; c4 < 4; ++c4) {
        __syncthreads();
#pragma unroll
        for (int i = 0; i < 4; ++i) {
            int e = tid + i * 256;
            int lr = e >> 4, p4 = (e & 15) * 4;
            As[lr][p4 + 0] = tf32r(pa[i].x);
            As[lr][p4 + 1] = tf32r(pa[i].y);
            As[lr][p4 + 2] = tf32r(pa[i].z);
            As[lr][p4 + 3] = tf32r(pa[i].w);
        }
#pragma unroll
        for (int i = 0; i < 2; ++i) {
            int e = tid + i * 256;
            int p = e >> 3, d4 = (e & 7) * 4;
            Bs[p][d4 + 0] = tf32r(pb[i].x);
            Bs[p][d4 + 1] = tf32r(pb[i].y);
            Bs[p][d4 + 2] = tf32r(pb[i].z);
            Bs[p][d4 + 3] = tf32r(pb[i].w);
        }
        __syncthreads();
        if (c4 < 3) {
            int pc = pbase + (c4 + 1) * 64;
#pragma unroll
            for (int i = 0; i < 4; ++i) {
                int e = tid + i * 256;
                int lr = e >> 4, p4 = (e & 15) * 4;
                pa[i] = *(const float4*)&g_probs[(((size_t)b * 32 + h) * 64 + lr) * 512 + pc + p4];
            }
#pragma unroll
            for (int i = 0; i < 2; ++i) {
                int e = tid + i * 256;
                int p = e >> 3, d4 = (e & 7) * 4;
                pb[i] = *(const float4*)&g_cv[((size_t)(b * 512 + pc + p)) * 512 + h * 32 + d4];
            }
        }
#pragma unroll
        for (int kt = 0; kt < 8; ++kt) {
            const int kb = kt * 8;
            int rA = mi * 16;
            unsigned a0 = __float_as_uint(As[rA + g][kb + t]);
            unsigned a1 = __float_as_uint(As[rA + g + 8][kb + t]);
            unsigned a2 = __float_as_uint(As[rA + g][kb + t + 4]);
            unsigned a3 = __float_as_uint(As[rA + g + 8][kb + t + 4]);
#pragma unroll
            for (int nt = 0; nt < 2; ++nt) {
                int nb = ni * 16 + nt * 8;
                unsigned b0 = __float_as_uint(Bs[kb + t][nb + g]);
                unsigned b1 = __float_as_uint(Bs[kb + t + 4][nb + g]);
                mma8(acc[nt], a0, a1, a2, a3, b0, b1);
            }
        }
    }
#pragma unroll
    for (int nt = 0; nt < 2; ++nt) {
        int r = mi * 16 + g;
        int c = ni * 16 + nt * 8 + 2 * t;
        size_t base = ((size_t)(b * 64 + r)) * 512 + h * 32 + c;
        *(float2*)&outp[base] = make_float2(acc[nt][0], acc[nt][1]);
        *(float2*)&outp[base + (size_t)8 * 512] = make_float2(acc[nt][2], acc[nt][3]);
    }
}

// ---------------- launch -------------------------------------------------------
extern "C" void kernel_launch(void* const* d_in, const int* in_sizes, int n_in,
                              void* d_out, int out_size)
{
    (void)in_sizes; (void)n_in; (void)out_size;
    const float* h_ligand = (const float*)d_in[0];
    const float* context  = (const float*)d_in[1];
    const float* xp       = (const float*)d_in[2];
    const float* xl       = (const float*)d_in[3];
    const float* w_qk     = (const float*)d_in[4];
    // d_in[5] = w_v (unused by the reference)
    const float* w_cqk    = (const float*)d_in[6];
    const float* w_cv     = (const float*)d_in[7];
    const float* w_mlp1   = (const float*)d_in[8];
    const float* w_mlp2   = (const float*)d_in[9];
    const float* b_mlp2   = (const float*)d_in[10];
    const float* w_out    = (const float*)d_in[11];
    const float* b_out    = (const float*)d_in[12];
    const float* w_dis1   = (const float*)d_in[13];
    const float* b_dis1   = (const float*)d_in[14];
    const float* w_dis2   = (const float*)d_in[15];
    const float* b_dis2   = (const float*)d_in[16];
    const float* sigma    = (const float*)d_in[17];
    const float* w_pe1    = (const float*)d_in[18];
    const float* b_pe1    = (const float*)d_in[19];
    const float* w_pe2    = (const float*)d_in[20];
    const float* b_pe2    = (const float*)d_in[21];
    float* out = (float*)d_out;

    void *p_qk, *p_cqk, *p_cv, *p_outpre, *p_outpre2;
    cudaGetSymbolAddress(&p_qk, g_qk);
    cudaGetSymbolAddress(&p_cqk, g_cqk);
    cudaGetSymbolAddress(&p_cv, g_cv);
    cudaGetSymbolAddress(&p_outpre, g_outpre);
    cudaGetSymbolAddress(&p_outpre2, g_outpre2);

    // #1 all three projections in ONE launch (544 blocks, register-prefetch)
    tgemm_all<<<544, 256>>>(context, h_ligand, w_cqk, w_cv, w_qk,
                            (float*)p_cqk, (float*)p_cv, (float*)p_qk);
    // #2 similarity scores (tf32 mma)
    sim_mma_kernel<<<dim3(2, 16, 16), 256>>>();

    // #3 fused pairwise MLPs + softmax + distance path (banked R7 config)
    const int sm4_bytes = SM4_FLOATS * (int)sizeof(float);
    cudaFuncSetAttribute(pair_kernel, cudaFuncAttributeMaxDynamicSharedMemorySize, sm4_bytes);
    pair_kernel<<<dim3(64, 16), 256, sm4_bytes>>>(
        xp, xl, w_mlp1, w_mlp2, b_mlp2, sigma, w_pe1, b_pe1, w_pe2, b_pe2,
        w_dis1, b_dis1, w_dis2, b_dis2, out);

    // #4 context path: attn @ cv (tf32 mma, k-split x2, pipelined)
    outagg_mma_kernel<<<dim3(16, 16, 2), 256>>>();
    // #5 out-proj (+bias, sums 2 partials) into d_out — 256 blocks x 4 rows
    outproj_kernel<<<256, 256>>>((const float*)p_outpre, (const float*)p_outpre2,
                                 w_out, b_out, out);
}

// round 15
// speedup vs baseline: 1.1010x; 1.0795x over previous
#include <cuda_runtime.h>
#include <cstddef>

#define OUT0 131072 // 1024*128, offset of out_dis in d_out

typedef unsigned long long u64;

// ---------------- scratch (device globals; no allocation allowed) -------------
__device__ float g_qk[1024 * 512];            // [B*L][INNER]
__device__ float g_cqk[8192 * 512];           // [B*P][INNER]
__device__ float g_cv[8192 * 512];            // [B*P][INNER]
__device__ float g_sim[16 * 16 * 64 * 512];   // [b][h][l][p] (scaled)
__device__ float g_probs[16 * 32 * 64 * 512]; // [b][c][l][p] (only c<16 written)
__device__ float g_outpre[1024 * 512];        // partial 0 (p 0..255)
__device__ float g_outpre2[1024 * 512];       // partial 1 (p 256..511)

// mish(x) = x*tanh(softplus(x)) = x * u/(u+2), u = e^x*(e^x+2)  (exact identity)
__device__ __forceinline__ float mishf(float x) {
    float t = __expf(fminf(x, 8.0f));
    float u = t * (t + 2.0f);
    return x * __fdividef(u, u + 2.0f);
}

__device__ __forceinline__ float tf32r(float x) {
    unsigned u;
    asm("cvt.rna.tf32.f32 %0, %1;" : "=r"(u) : "f"(x));
    return __uint_as_float(u);
}

__device__ __forceinline__ void mma8(float* c, unsigned a0, unsigned a1,
                                     unsigned a2, unsigned a3,
                                     unsigned b0, unsigned b1) {
    asm volatile(
        "mma.sync.aligned.m16n8k8.row.col.f32.tf32.tf32.f32 "
        "{%0,%1,%2,%3},{%4,%5,%6,%7},{%8,%9},{%0,%1,%2,%3};"
        : "+f"(c[0]), "+f"(c[1]), "+f"(c[2]), "+f"(c[3])
        : "r"(a0), "r"(a1), "r"(a2), "r"(a3), "r"(b0), "r"(b1));
}

// ---- packed f32x2 helpers (Blackwell FFMA2 — only reachable via PTX) ---------
__device__ __forceinline__ u64 ffma2(u64 a, u64 b, u64 c) {
    u64 d;
    asm("fma.rn.f32x2 %0, %1, %2, %3;" : "=l"(d) : "l"(a), "l"(b), "l"(c));
    return d;
}
__device__ __forceinline__ u64 pk2(float x, float y) {
    u64 r;
    asm("mov.b64 %0, {%1, %2};" : "=l"(r) : "f"(x), "f"(y));
    return r;
}
__device__ __forceinline__ float2 up2(u64 v) {
    float2 r;
    asm("mov.b64 {%0, %1}, %2;" : "=f"(r.x), "=f"(r.y) : "l"(v));
    return r;
}

// ------ unified tf32 GEMM launch: blocks 0..511 cqk|cv (K=256), 512..543 qk ----
// Software-pipelined: next k-slab's global loads issued before the mma phase.
__global__ void __launch_bounds__(256) tgemm_all(
    const float* __restrict__ ctx, const float* __restrict__ hlig,
    const float* __restrict__ w_cqk, const float* __restrict__ w_cv,
    const float* __restrict__ w_qk,
    float* __restrict__ cqk, float* __restrict__ cv, float* __restrict__ qk)
{
    __shared__ float As[128][36];
    __shared__ float Bs[32][136];
    const int tid = threadIdx.x;
    const int lane = tid & 31, warp = tid >> 5;
    const int wm = warp >> 1, wn = warp & 1;
    const int g = lane >> 2, t = lane & 3;
    const int N = 512;

    int bid = blockIdx.x;
    const float* A; const float* Bm; float* C;
    int row0, col0, K;
    if (bid < 512) {
        row0 = (bid >> 3) * 128; col0 = (bid & 7) * 128;
        A = ctx; K = 256;
        if (col0 >= 512) { Bm = w_cv; C = cv; col0 -= 512; }
        else             { Bm = w_cqk; C = cqk; }
    } else {
        int b2 = bid - 512;
        row0 = (b2 >> 2) * 128; col0 = (b2 & 3) * 128;
        A = hlig; Bm = w_qk; C = qk; K = 128;
    }

    float acc[2][8][4];
#pragma unroll
    for (int mt = 0; mt < 2; ++mt)
#pragma unroll
        for (int nt = 0; nt < 8; ++nt)
#pragma unroll
            for (int q = 0; q < 4; ++q) acc[mt][nt][q] = 0.f;

    float4 va[4], vb[4];
    // prologue: load slab 0
#pragma unroll
    for (int i = 0; i < 4; ++i) {
        int f4 = tid + i * 256;
        int r = f4 >> 3, kc = (f4 & 7) * 4;
        va[i] = *(const float4*)&A[(size_t)(row0 + r) * K + kc];
        int kk = f4 >> 5, nc = (f4 & 31) * 4;
        vb[i] = *(const float4*)&Bm[(size_t)kk * N + col0 + nc];
    }

    for (int k0 = 0; k0 < K; k0 += 32) {
        __syncthreads();
#pragma unroll
        for (int i = 0; i < 4; ++i) {
            int f4 = tid + i * 256;
            int r = f4 >> 3, kc = (f4 & 7) * 4;
            As[r][kc + 0] = tf32r(va[i].x);
            As[r][kc + 1] = tf32r(va[i].y);
            As[r][kc + 2] = tf32r(va[i].z);
            As[r][kc + 3] = tf32r(va[i].w);
            int kk = f4 >> 5, nc = (f4 & 31) * 4;
            Bs[kk][nc + 0] = tf32r(vb[i].x);
            Bs[kk][nc + 1] = tf32r(vb[i].y);
            Bs[kk][nc + 2] = tf32r(vb[i].z);
            Bs[kk][nc + 3] = tf32r(vb[i].w);
        }
        __syncthreads();
        // prefetch next slab while mma runs
        if (k0 + 32 < K) {
            int kn = k0 + 32;
#pragma unroll
            for (int i = 0; i < 4; ++i) {
                int f4 = tid + i * 256;
                int r = f4 >> 3, kc = (f4 & 7) * 4;
                va[i] = *(const float4*)&A[(size_t)(row0 + r) * K + kn + kc];
                int kk = f4 >> 5, nc = (f4 & 31) * 4;
                vb[i] = *(const float4*)&Bm[(size_t)(kn + kk) * N + col0 + nc];
            }
        }
#pragma unroll
        for (int ks = 0; ks < 4; ++ks) {
            const int kb = ks * 8;
            unsigned a[2][4];
#pragma unroll
            for (int mt = 0; mt < 2; ++mt) {
                int rb = wm * 32 + mt * 16;
                a[mt][0] = __float_as_uint(As[rb + g][kb + t]);
                a[mt][1] = __float_as_uint(As[rb + g + 8][kb + t]);
                a[mt][2] = __float_as_uint(As[rb + g][kb + t + 4]);
                a[mt][3] = __float_as_uint(As[rb + g + 8][kb + t + 4]);
            }
#pragma unroll
            for (int nt = 0; nt < 8; ++nt) {
                int nb = wn * 64 + nt * 8;
                unsigned b0 = __float_as_uint(Bs[kb + t][nb + g]);
                unsigned b1 = __float_as_uint(Bs[kb + t + 4][nb + g]);
#pragma unroll
                for (int mt = 0; mt < 2; ++mt)
                    mma8(acc[mt][nt], a[mt][0], a[mt][1], a[mt][2], a[mt][3], b0, b1);
            }
        }
    }
#pragma unroll
    for (int mt = 0; mt < 2; ++mt) {
#pragma unroll
        for (int nt = 0; nt < 8; ++nt) {
            int r = row0 + wm * 32 + mt * 16 + g;
            int c = col0 + wn * 64 + nt * 8 + 2 * t;
            __stcs((float2*)&C[(size_t)r * N + c],
                   make_float2(acc[mt][nt][0], acc[mt][nt][1]));
            __stcs((float2*)&C[(size_t)(r + 8) * N + c],
                   make_float2(acc[mt][nt][2], acc[mt][nt][3]));
        }
    }
}

// ------- out-proj (R11-proven): 2 rows x 512 blocks ---------------------------
__global__ void __launch_bounds__(256) outproj_kernel(
    const float* __restrict__ A0, const float* __restrict__ A1,
    const float* __restrict__ B,
    const float* __restrict__ bias, float* __restrict__ C)
{
    __shared__ float As[2][512];
    const int tid = threadIdx.x;
    const int r0 = blockIdx.x * 2;
    {
        float4 a = __ldcs(&((const float4*)&A0[(size_t)r0 * 512])[tid]);
        float4 b = __ldcs(&((const float4*)&A1[(size_t)r0 * 512])[tid]);
        a.x += b.x; a.y += b.y; a.z += b.z; a.w += b.w;
        ((float4*)&As[0][0])[tid] = a;
    }
    __syncthreads();
    const int row = tid >> 7, c = tid & 127;
    const float* arow = As[row];
    float acc = bias[c];
    const float* bp = B + c;
#pragma unroll 8
    for (int k = 0; k < 512; k += 4) {
        float4 a = *(const float4*)&arow[k];
        acc += a.x * bp[(size_t)(k + 0) * 128];
        acc += a.y * bp[(size_t)(k + 1) * 128];
        acc += a.z * bp[(size_t)(k + 2) * 128];
        acc += a.w * bp[(size_t)(k + 3) * 128];
    }
    C[(size_t)(r0 + row) * 128 + c] = acc;
}

// ---------------- sim via tf32 mma: per (p-half, h, b) 64x256x32 --------------
__global__ void __launch_bounds__(256) sim_mma_kernel()
{
    __shared__ float As[64 * 34];   // [l][d]
    __shared__ float Bs[32 * 258];  // [d][p] (transposed)
    const int ph = blockIdx.x, h = blockIdx.y, b = blockIdx.z;
    const int tid = threadIdx.x;
    const int w = tid >> 5, lane = tid & 31, g = lane >> 2, t = lane & 3;

    for (int e = tid; e < 2048; e += 256) {
        int lr = e >> 5, d = e & 31;
        As[lr * 34 + d] = tf32r(g_qk[((size_t)(b * 64 + lr)) * 512 + h * 32 + d]);
    }
    for (int e = tid; e < 8192; e += 256) {
        int p = e >> 5, d = e & 31;
        Bs[d * 258 + p] = tf32r(g_cqk[((size_t)(b * 512 + ph * 256 + p)) * 512 + h * 32 + d]);
    }
    __syncthreads();

    float acc[4][4][4];
#pragma unroll
    for (int mi = 0; mi < 4; ++mi)
#pragma unroll
        for (int nt = 0; nt < 4; ++nt)
#pragma unroll
            for (int q = 0; q < 4; ++q) acc[mi][nt][q] = 0.f;

    const int n0 = w * 32;
#pragma unroll
    for (int kt = 0; kt < 4; ++kt) {
        const int kb = kt * 8;
        unsigned aF[4][4];
#pragma unroll
        for (int mi = 0; mi < 4; ++mi) {
            int rA = mi * 16;
            aF[mi][0] = __float_as_uint(As[(rA + g) * 34 + kb + t]);
            aF[mi][1] = __float_as_uint(As[(rA + g + 8) * 34 + kb + t]);
            aF[mi][2] = __float_as_uint(As[(rA + g) * 34 + kb + t + 4]);
            aF[mi][3] = __float_as_uint(As[(rA + g + 8) * 34 + kb + t + 4]);
        }
#pragma unroll
        for (int nt = 0; nt < 4; ++nt) {
            int nb = n0 + nt * 8;
            unsigned b0 = __float_as_uint(Bs[(kb + t) * 258 + nb + g]);
            unsigned b1 = __float_as_uint(Bs[(kb + t + 4) * 258 + nb + g]);
#pragma unroll
            for (int mi = 0; mi < 4; ++mi)
                mma8(acc[mi][nt], aF[mi][0], aF[mi][1], aF[mi][2], aF[mi][3], b0, b1);
        }
    }
    const float SCALE = 0.17677669529663687f; // 32^-0.5
#pragma unroll
    for (int mi = 0; mi < 4; ++mi)
#pragma unroll
        for (int nt = 0; nt < 4; ++nt) {
            int lr = mi * 16 + g;
            int pc = ph * 256 + n0 + nt * 8 + 2 * t;
            size_t base = (((size_t)(b * 16 + h)) * 64 + lr) * 512 + pc;
            __stcs((float2*)&g_sim[base],
                   make_float2(acc[mi][nt][0] * SCALE, acc[mi][nt][1] * SCALE));
            __stcs((float2*)&g_sim[base + (size_t)8 * 512],
                   make_float2(acc[mi][nt][2] * SCALE, acc[mi][nt][3] * SCALE));
        }
}

// ------- fused pairwise MLPs + softmax + distance path (FFMA2, 2 p/thread) ----
#define SM4_FLOATS (512 * 33 + 2048 + 2048 + 256 + 1024 + 64 + 16 + 32 + 1536 + 48 + 96)
__global__ void __launch_bounds__(256) pair_kernel(
    const float* __restrict__ xp, const float* __restrict__ xl,
    const float* __restrict__ w_mlp1, const float* __restrict__ w_mlp2,
    const float* __restrict__ b_mlp2, const float* __restrict__ sigma,
    const float* __restrict__ w_pe1, const float* __restrict__ b_pe1,
    const float* __restrict__ w_pe2, const float* __restrict__ b_pe2,
    const float* __restrict__ w_dis1, const float* __restrict__ b_dis1,
    const float* __restrict__ w_dis2, const float* __restrict__ b_dis2,
    float* __restrict__ out)
{
    extern __shared__ float sm[];
    float* lg    = sm;                 // 512*33 logits -> probs(c>=16)
    float* w1t   = lg + 512 * 33;      // [k][i] transposed w_mlp1, 64*32
    float* w2s   = w1t + 2048;         // w_mlp2 as-is, 64*32
    float* wpe1t = w2s + 2048;         // [k][i(pad4)], 64*4
    float* wpe2s = wpe1t + 256;        // w_pe2 as-is, 64*16
    float* bpe1s = wpe2s + 1024;       // 64
    float* bpe2s = bpe1s + 64;         // 16
    float* bm2s  = bpe2s + 16;         // 32
    float* xps   = bm2s + 32;          // [512][3] raw protein coords
    float* ods   = xps + 1536;         // [3][16]
    float* zs    = ods + 48;           // [3][32]

    const int tid = threadIdx.x;
    const int l = blockIdx.x, b = blockIdx.y;

    for (int e = tid; e < 2048; e += 256) { int i = e >> 6, k = e & 63; w1t[k * 32 + i] = w_mlp1[e]; }
    for (int e = tid; e < 2048; e += 256) w2s[e] = w_mlp2[e];
    if (tid < 192) { int i = tid >> 6, k = tid & 63; wpe1t[k * 4 + i] = w_pe1[tid]; }
    for (int e = tid; e < 1024; e += 256) wpe2s[e] = w_pe2[e];
    if (tid < 64) bpe1s[tid] = b_pe1[tid];
    if (tid < 16) bpe2s[tid] = b_pe2[tid];
    if (tid < 32) bm2s[tid]  = b_mlp2[tid];
    __syncthreads();

    const float sg = sigma[0];
    const float cpe = -0.5f / (sg * sg);
    const int rowl = b * 64 + l;
    const float xl0 = xl[rowl * 3 + 0], xl1 = xl[rowl * 3 + 1], xl2 = xl[rowl * 3 + 2];

    const int p0 = tid, p1 = tid + 256;

    // s pairs for both p: [0..7] sim heads, [8..15] dis_emb
    u64 sp0[16], sp1[16];
    {
        size_t base = (((size_t)b * 16) * 64 + l) * 512;
#pragma unroll
        for (int h2 = 0; h2 < 8; ++h2) {
            size_t o0 = base + (size_t)(2 * h2) * 64 * 512;
            size_t o1 = base + (size_t)(2 * h2 + 1) * 64 * 512;
            sp0[h2] = pk2(__ldcs(&g_sim[o0 + p0]), __ldcs(&g_sim[o1 + p0]));
            sp1[h2] = pk2(__ldcs(&g_sim[o0 + p1]), __ldcs(&g_sim[o1 + p1]));
        }
    }

    // positional-encoding MLP: 3 -> 64 (mish) -> 16, both p share weight loads
    {
        const float* xpr0 = xp + (size_t)(b * 512 + p0) * 3;
        const float* xpr1 = xp + (size_t)(b * 512 + p1) * 3;
        float xA0 = xpr0[0], xA1 = xpr0[1], xA2 = xpr0[2];
        float xB0 = xpr1[0], xB1 = xpr1[1], xB2 = xpr1[2];
        xps[p0 * 3 + 0] = xA0; xps[p0 * 3 + 1] = xA1; xps[p0 * 3 + 2] = xA2;
        xps[p1 * 3 + 0] = xB0; xps[p1 * 3 + 1] = xB1; xps[p1 * 3 + 2] = xB2;

        float peA0 = __expf(cpe * (xA0 - xl0));
        float peA1 = __expf(cpe * (xA1 - xl1));
        float peA2 = __expf(cpe * (xA2 - xl2));
        float peB0 = __expf(cpe * (xB0 - xl0));
        float peB1 = __expf(cpe * (xB1 - xl1));
        float peB2 = __expf(cpe * (xB2 - xl2));

        u64 deA[8], deB[8];
#pragma unroll
        for (int j = 0; j < 8; ++j) {
            u64 bb = pk2(bpe2s[2 * j], bpe2s[2 * j + 1]);
            deA[j] = bb; deB[j] = bb;
        }
#pragma unroll 2
        for (int k = 0; k < 64; ++k) {
            float w0 = wpe1t[k * 4], w1 = wpe1t[k * 4 + 1], w2 = wpe1t[k * 4 + 2];
            float bk = bpe1s[k];
            float hA = bk + peA0 * w0 + peA1 * w1 + peA2 * w2;
            float hB = bk + peB0 * w0 + peB1 * w1 + peB2 * w2;
            float mA = mishf(hA), mB = mishf(hB);
            u64 mA2 = pk2(mA, mA), mB2 = pk2(mB, mB);
            const ulonglong2* wr = (const ulonglong2*)(wpe2s + k * 16);
#pragma unroll
            for (int q = 0; q < 4; ++q) {
                ulonglong2 w = wr[q];
                deA[2 * q + 0] = ffma2(mA2, w.x, deA[2 * q + 0]);
                deA[2 * q + 1] = ffma2(mA2, w.y, deA[2 * q + 1]);
                deB[2 * q + 0] = ffma2(mB2, w.x, deB[2 * q + 0]);
                deB[2 * q + 1] = ffma2(mB2, w.y, deB[2 * q + 1]);
            }
        }
#pragma unroll
        for (int j = 0; j < 8; ++j) { sp0[8 + j] = deA[j]; sp1[8 + j] = deB[j]; }
    }

    // attention MLP: 32 -> 64 (mish) -> 32, single pass, split h-chains for ILP
    const u64 z2 = pk2(0.f, 0.f);
    u64 oA[16], oB[16];
#pragma unroll
    for (int j = 0; j < 16; ++j) {
        u64 bb = pk2(bm2s[2 * j], bm2s[2 * j + 1]);
        oA[j] = bb; oB[j] = bb;
    }
#pragma unroll 2
    for (int k = 0; k < 64; ++k) {
        const ulonglong2* w1r = (const ulonglong2*)(w1t + k * 32);
        u64 hA0 = z2, hA1 = z2, hB0 = z2, hB1 = z2;
#pragma unroll
        for (int q = 0; q < 4; ++q) {
            ulonglong2 w = w1r[q];
            hA0 = ffma2(sp0[2 * q + 0], w.x, hA0);
            hA0 = ffma2(sp0[2 * q + 1], w.y, hA0);
            hB0 = ffma2(sp1[2 * q + 0], w.x, hB0);
            hB0 = ffma2(sp1[2 * q + 1], w.y, hB0);
        }
#pragma unroll
        for (int q = 4; q < 8; ++q) {
            ulonglong2 w = w1r[q];
            hA1 = ffma2(sp0[2 * q + 0], w.x, hA1);
            hA1 = ffma2(sp0[2 * q + 1], w.y, hA1);
            hB1 = ffma2(sp1[2 * q + 0], w.x, hB1);
            hB1 = ffma2(sp1[2 * q + 1], w.y, hB1);
        }
        float2 a0 = up2(hA0), a1 = up2(hA1);
        float2 b0 = up2(hB0), b1 = up2(hB1);
        float mA = mishf((a0.x + a0.y) + (a1.x + a1.y));
        float mB = mishf((b0.x + b0.y) + (b1.x + b1.y));
        u64 mA2 = pk2(mA, mA), mB2 = pk2(mB, mB);
        const ulonglong2* w2r = (const ulonglong2*)(w2s + k * 32);
#pragma unroll
        for (int q = 0; q < 8; ++q) {
            ulonglong2 w = w2r[q];
            oA[2 * q + 0] = ffma2(mA2, w.x, oA[2 * q + 0]);
            oA[2 * q + 1] = ffma2(mA2, w.y, oA[2 * q + 1]);
            oB[2 * q + 0] = ffma2(mB2, w.x, oB[2 * q + 0]);
            oB[2 * q + 1] = ffma2(mB2, w.y, oB[2 * q + 1]);
        }
    }
#pragma unroll
    for (int j = 0; j < 16; ++j) {
        float2 vA = up2(oA[j]);
        float2 vB = up2(oB[j]);
        lg[p0 * 33 + 2 * j + 0] = vA.x;
        lg[p0 * 33 + 2 * j + 1] = vA.y;
        lg[p1 * 33 + 2 * j + 0] = vB.x;
        lg[p1 * 33 + 2 * j + 1] = vB.y;
    }
    __syncthreads();

    // softmax: warp w owns channels 4w..4w+3; c<16 -> g_probs, c>=16 -> lg smem
    const int w = tid >> 5, lane = tid & 31;
#pragma unroll
    for (int cc = 0; cc < 4; ++cc) {
        int c = w * 4 + cc;
        float mx = -3.4e38f;
#pragma unroll
        for (int i = 0; i < 16; ++i) mx = fmaxf(mx, lg[(lane + i * 32) * 33 + c]);
#pragma unroll
        for (int off = 16; off; off >>= 1) mx = fmaxf(mx, __shfl_xor_sync(0xffffffffu, mx, off));
        float ev[16]; float sum = 0.f;
#pragma unroll
        for (int i = 0; i < 16; ++i) {
            ev[i] = __expf(lg[(lane + i * 32) * 33 + c] - mx);
            sum += ev[i];
        }
#pragma unroll
        for (int off = 16; off; off >>= 1) sum += __shfl_xor_sync(0xffffffffu, sum, off);
        float inv = 1.0f / sum;
        if (c < 16) {
            size_t base = (((size_t)b * 32 + c) * 64 + l) * 512;
#pragma unroll
            for (int i = 0; i < 16; ++i)
                __stcs(&g_probs[base + lane + i * 32], ev[i] * inv);
        } else {
#pragma unroll
            for (int i = 0; i < 16; ++i) lg[(lane + i * 32) * 33 + c] = ev[i] * inv;
        }
    }
    __syncthreads();

    // ---- fused distance path: Σ_p prob·xp − xl, then tiny MLP into d_out ----
#pragma unroll
    for (int q = 0; q < 6; ++q) {
        int idx = w * 6 + q;
        int i = idx >> 4, h = idx & 15;
        float sum = 0.f;
#pragma unroll
        for (int it = 0; it < 16; ++it) {
            int p = lane + it * 32;
            sum += lg[p * 33 + 16 + h] * xps[p * 3 + i];
        }
#pragma unroll
        for (int off = 16; off; off >>= 1) sum += __shfl_xor_sync(0xffffffffu, sum, off);
        if (lane == 0) {
            float xli = (i == 0) ? xl0 : ((i == 1) ? xl1 : xl2);
            ods[i * 16 + h] = sum - xli;
        }
    }
    __syncthreads();
    if (tid < 96) {
        int i = tid >> 5, k = tid & 31;
        float hz = b_dis1[k];
#pragma unroll
        for (int j = 0; j < 16; ++j) hz += ods[i * 16 + j] * w_dis1[j * 32 + k];
        zs[i * 32 + k] = mishf(hz);
    }
    __syncthreads();
    if (tid < 48) {
        int i = tid / 16, h = tid % 16;
        float y = b_dis2[h];
#pragma unroll
        for (int k = 0; k < 32; ++k) y += zs[i * 32 + k] * w_dis2[k * 16 + h];
        out[OUT0 + (((size_t)b * 64 + l) * 3 + i) * 16 + h] = y;
    }
}

// ---- outagg via tf32 mma, k-split x2 + register-prefetch pipeline ------------
__global__ void __launch_bounds__(256) outagg_mma_kernel()
{
    __shared__ float As[64][68];
    __shared__ float Bs[64][40];
    const int b = blockIdx.x, h = blockIdx.y, z = blockIdx.z;
    const int tid = threadIdx.x;
    const int w = tid >> 5, lane = tid & 31, g = lane >> 2, t = lane & 3;
    const int mi = w >> 1, ni = w & 1;
    const int pbase = z * 256;
    float* outp = z ? g_outpre2 : g_outpre;

    float acc[2][4];
#pragma unroll
    for (int nt = 0; nt < 2; ++nt)
#pragma unroll
        for (int q = 0; q < 4; ++q) acc[nt][q] = 0.f;

    float4 pa[4], pb[2];
#pragma unroll
    for (int i = 0; i < 4; ++i) {
        int e = tid + i * 256;
        int lr = e >> 4, p4 = (e & 15) * 4;
        pa[i] = __ldcs((const float4*)&g_probs[(((size_t)b * 32 + h) * 64 + lr) * 512 + pbase + p4]);
    }
#pragma unroll
    for (int i = 0; i < 2; ++i) {
        int e = tid + i * 256;
        int p = e >> 3, d4 = (e & 7) * 4;
        pb[i] = __ldcs((const float4*)&g_cv[((size_t)(b * 512 + pbase + p)) * 512 + h * 32 + d4]);
    }

    for (int c4 = 0; c4 < 4; ++c4) {
        __syncthreads();
#pragma unroll
        for (int i = 0; i < 4; ++i) {
            int e = tid + i * 256;
            int lr = e >> 4, p4 = (e & 15) * 4;
            As[lr][p4 + 0] = tf32r(pa[i].x);
            As[lr][p4 + 1] = tf32r(pa[i].y);
            As[lr][p4 + 2] = tf32r(pa[i].z);
            As[lr][p4 + 3] = tf32r(pa[i].w);
        }
#pragma unroll
        for (int i = 0; i < 2; ++i) {
            int e = tid + i * 256;
            int p = e >> 3, d4 = (e & 7) * 4;
            Bs[p][d4 + 0] = tf32r(pb[i].x);
            Bs[p][d4 + 1] = tf32r(pb[i].y);
            Bs[p][d4 + 2] = tf32r(pb[i].z);
            Bs[p][d4 + 3] = tf32r(pb[i].w);
        }
        __syncthreads();
        if (c4 < 3) {
            int pc = pbase + (c4 + 1) * 64;
#pragma unroll
            for (int i = 0; i < 4; ++i) {
                int e = tid + i * 256;
                int lr = e >> 4, p4 = (e & 15) * 4;
                pa[i] = __ldcs((const float4*)&g_probs[(((size_t)b * 32 + h) * 64 + lr) * 512 + pc + p4]);
            }
#pragma unroll
            for (int i = 0; i < 2; ++i) {
                int e = tid + i * 256;
                int p = e >> 3, d4 = (e & 7) * 4;
                pb[i] = __ldcs((const float4*)&g_cv[((size_t)(b * 512 + pc + p)) * 512 + h * 32 + d4]);
            }
        }
#pragma unroll
        for (int kt = 0; kt < 8; ++kt) {
            const int kb = kt * 8;
            int rA = mi * 16;
            unsigned a0 = __float_as_uint(As[rA + g][kb + t]);
            unsigned a1 = __float_as_uint(As[rA + g + 8][kb + t]);
            unsigned a2 = __float_as_uint(As[rA + g][kb + t + 4]);
            unsigned a3 = __float_as_uint(As[rA + g + 8][kb + t + 4]);
#pragma unroll
            for (int nt = 0; nt < 2; ++nt) {
                int nb = ni * 16 + nt * 8;
                unsigned b0 = __float_as_uint(Bs[kb + t][nb + g]);
                unsigned b1 = __float_as_uint(Bs[kb + t + 4][nb + g]);
                mma8(acc[nt], a0, a1, a2, a3, b0, b1);
            }
        }
    }
#pragma unroll
    for (int nt = 0; nt < 2; ++nt) {
        int r = mi * 16 + g;
        int c = ni * 16 + nt * 8 + 2 * t;
        size_t base = ((size_t)(b * 64 + r)) * 512 + h * 32 + c;
        __stcs((float2*)&outp[base], make_float2(acc[nt][0], acc[nt][1]));
        __stcs((float2*)&outp[base + (size_t)8 * 512], make_float2(acc[nt][2], acc[nt][3]));
    }
}

// ---------------- launch -------------------------------------------------------
extern "C" void kernel_launch(void* const* d_in, const int* in_sizes, int n_in,
                              void* d_out, int out_size)
{
    (void)in_sizes; (void)n_in; (void)out_size;
    const float* h_ligand = (const float*)d_in[0];
    const float* context  = (const float*)d_in[1];
    const float* xp       = (const float*)d_in[2];
    const float* xl       = (const float*)d_in[3];
    const float* w_qk     = (const float*)d_in[4];
    // d_in[5] = w_v (unused by the reference)
    const float* w_cqk    = (const float*)d_in[6];
    const float* w_cv     = (const float*)d_in[7];
    const float* w_mlp1   = (const float*)d_in[8];
    const float* w_mlp2   = (const float*)d_in[9];
    const float* b_mlp2   = (const float*)d_in[10];
    const float* w_out    = (const float*)d_in[11];
    const float* b_out    = (const float*)d_in[12];
    const float* w_dis1   = (const float*)d_in[13];
    const float* b_dis1   = (const float*)d_in[14];
    const float* w_dis2   = (const float*)d_in[15];
    const float* b_dis2   = (const float*)d_in[16];
    const float* sigma    = (const float*)d_in[17];
    const float* w_pe1    = (const float*)d_in[18];
    const float* b_pe1    = (const float*)d_in[19];
    const float* w_pe2    = (const float*)d_in[20];
    const float* b_pe2    = (const float*)d_in[21];
    float* out = (float*)d_out;

    void *p_qk, *p_cqk, *p_cv, *p_outpre, *p_outpre2;
    cudaGetSymbolAddress(&p_qk, g_qk);
    cudaGetSymbolAddress(&p_cqk, g_cqk);
    cudaGetSymbolAddress(&p_cv, g_cv);
    cudaGetSymbolAddress(&p_outpre, g_outpre);
    cudaGetSymbolAddress(&p_outpre2, g_outpre2);

    // #1 all three projections in ONE launch (544 blocks, register-prefetch)
    tgemm_all<<<544, 256>>>(context, h_ligand, w_cqk, w_cv, w_qk,
                            (float*)p_cqk, (float*)p_cv, (float*)p_qk);
    // #2 similarity scores (tf32 mma)
    sim_mma_kernel<<<dim3(2, 16, 16), 256>>>();

    // #3 fused pairwise MLPs + softmax + distance path (banked R7 config)
    const int sm4_bytes = SM4_FLOATS * (int)sizeof(float);
    cudaFuncSetAttribute(pair_kernel, cudaFuncAttributeMaxDynamicSharedMemorySize, sm4_bytes);
    pair_kernel<<<dim3(64, 16), 256, sm4_bytes>>>(
        xp, xl, w_mlp1, w_mlp2, b_mlp2, sigma, w_pe1, b_pe1, w_pe2, b_pe2,
        w_dis1, b_dis1, w_dis2, b_dis2, out);

    // #4 context path: attn @ cv (tf32 mma, k-split x2, pipelined)
    outagg_mma_kernel<<<dim3(16, 16, 2), 256>>>();
    // #5 out-proj (+bias, sums 2 partials) into d_out — 512 blocks x 2 rows
    outproj_kernel<<<512, 256>>>((const float*)p_outpre, (const float*)p_outpre2,
                                 w_out, b_out, out);
}

// round 16
// speedup vs baseline: 1.1157x; 1.0133x over previous
#include <cuda_runtime.h>
#include <cstddef>

#define OUT0 131072 // 1024*128, offset of out_dis in d_out

typedef unsigned long long u64;

// ---------------- scratch (device globals; no allocation allowed) -------------
__device__ float g_qk[1024 * 512];            // [B*L][INNER]
__device__ float g_cqk[8192 * 512];           // [B*P][INNER]
__device__ float g_cv[8192 * 512];            // [B*P][INNER]
__device__ float g_sim[16 * 16 * 64 * 512];   // [b][h][l][p] (scaled)
__device__ float g_probs[16 * 32 * 64 * 512]; // [b][c][l][p] (only c<16 written)
__device__ float g_outpre[1024 * 512];        // partial 0 (p 0..255)
__device__ float g_outpre2[1024 * 512];       // partial 1 (p 256..511)

// mish(x) = x*tanh(softplus(x)) = x * u/(u+2), u = e^x*(e^x+2)  (exact identity)
__device__ __forceinline__ float mishf(float x) {
    float t = __expf(fminf(x, 8.0f));
    float u = t * (t + 2.0f);
    return x * __fdividef(u, u + 2.0f);
}

__device__ __forceinline__ float tf32r(float x) {
    unsigned u;
    asm("cvt.rna.tf32.f32 %0, %1;" : "=r"(u) : "f"(x));
    return __uint_as_float(u);
}

__device__ __forceinline__ void mma8(float* c, unsigned a0, unsigned a1,
                                     unsigned a2, unsigned a3,
                                     unsigned b0, unsigned b1) {
    asm volatile(
        "mma.sync.aligned.m16n8k8.row.col.f32.tf32.tf32.f32 "
        "{%0,%1,%2,%3},{%4,%5,%6,%7},{%8,%9},{%0,%1,%2,%3};"
        : "+f"(c[0]), "+f"(c[1]), "+f"(c[2]), "+f"(c[3])
        : "r"(a0), "r"(a1), "r"(a2), "r"(a3), "r"(b0), "r"(b1));
}

// ---- packed f32x2 helpers (Blackwell FFMA2 — only reachable via PTX) ---------
__device__ __forceinline__ u64 ffma2(u64 a, u64 b, u64 c) {
    u64 d;
    asm("fma.rn.f32x2 %0, %1, %2, %3;" : "=l"(d) : "l"(a), "l"(b), "l"(c));
    return d;
}
__device__ __forceinline__ u64 pk2(float x, float y) {
    u64 r;
    asm("mov.b64 %0, {%1, %2};" : "=l"(r) : "f"(x), "f"(y));
    return r;
}
__device__ __forceinline__ float2 up2(u64 v) {
    float2 r;
    asm("mov.b64 {%0, %1}, %2;" : "=f"(r.x), "=f"(r.y) : "l"(v));
    return r;
}

// ------ unified tf32 GEMM launch: blocks 0..511 cqk|cv (K=256), 512..543 qk ----
// Software-pipelined: next k-slab's global loads issued before the mma phase.
__global__ void __launch_bounds__(256, 2) tgemm_all(
    const float* __restrict__ ctx, const float* __restrict__ hlig,
    const float* __restrict__ w_cqk, const float* __restrict__ w_cv,
    const float* __restrict__ w_qk,
    float* __restrict__ cqk, float* __restrict__ cv, float* __restrict__ qk)
{
    __shared__ float As[128][36];
    __shared__ float Bs[32][136];
    const int tid = threadIdx.x;
    const int lane = tid & 31, warp = tid >> 5;
    const int wm = warp >> 1, wn = warp & 1;
    const int g = lane >> 2, t = lane & 3;
    const int N = 512;

    int bid = blockIdx.x;
    const float* A; const float* Bm; float* C;
    int row0, col0, K;
    if (bid < 512) {
        row0 = (bid >> 3) * 128; col0 = (bid & 7) * 128;
        A = ctx; K = 256;
        if (col0 >= 512) { Bm = w_cv; C = cv; col0 -= 512; }
        else             { Bm = w_cqk; C = cqk; }
    } else {
        int b2 = bid - 512;
        row0 = (b2 >> 2) * 128; col0 = (b2 & 3) * 128;
        A = hlig; Bm = w_qk; C = qk; K = 128;
    }

    float acc[2][8][4];
#pragma unroll
    for (int mt = 0; mt < 2; ++mt)
#pragma unroll
        for (int nt = 0; nt < 8; ++nt)
#pragma unroll
            for (int q = 0; q < 4; ++q) acc[mt][nt][q] = 0.f;

    float4 va[4], vb[4];
    // prologue: load slab 0
#pragma unroll
    for (int i = 0; i < 4; ++i) {
        int f4 = tid + i * 256;
        int r = f4 >> 3, kc = (f4 & 7) * 4;
        va[i] = *(const float4*)&A[(size_t)(row0 + r) * K + kc];
        int kk = f4 >> 5, nc = (f4 & 31) * 4;
        vb[i] = *(const float4*)&Bm[(size_t)kk * N + col0 + nc];
    }

    for (int k0 = 0; k0 < K; k0 += 32) {
        __syncthreads();
#pragma unroll
        for (int i = 0; i < 4; ++i) {
            int f4 = tid + i * 256;
            int r = f4 >> 3, kc = (f4 & 7) * 4;
            As[r][kc + 0] = tf32r(va[i].x);
            As[r][kc + 1] = tf32r(va[i].y);
            As[r][kc + 2] = tf32r(va[i].z);
            As[r][kc + 3] = tf32r(va[i].w);
            int kk = f4 >> 5, nc = (f4 & 31) * 4;
            Bs[kk][nc + 0] = tf32r(vb[i].x);
            Bs[kk][nc + 1] = tf32r(vb[i].y);
            Bs[kk][nc + 2] = tf32r(vb[i].z);
            Bs[kk][nc + 3] = tf32r(vb[i].w);
        }
        __syncthreads();
        // prefetch next slab while mma runs
        if (k0 + 32 < K) {
            int kn = k0 + 32;
#pragma unroll
            for (int i = 0; i < 4; ++i) {
                int f4 = tid + i * 256;
                int r = f4 >> 3, kc = (f4 & 7) * 4;
                va[i] = *(const float4*)&A[(size_t)(row0 + r) * K + kn + kc];
                int kk = f4 >> 5, nc = (f4 & 31) * 4;
                vb[i] = *(const float4*)&Bm[(size_t)(kn + kk) * N + col0 + nc];
            }
        }
#pragma unroll
        for (int ks = 0; ks < 4; ++ks) {
            const int kb = ks * 8;
            unsigned a[2][4];
#pragma unroll
            for (int mt = 0; mt < 2; ++mt) {
                int rb = wm * 32 + mt * 16;
                a[mt][0] = __float_as_uint(As[rb + g][kb + t]);
                a[mt][1] = __float_as_uint(As[rb + g + 8][kb + t]);
                a[mt][2] = __float_as_uint(As[rb + g][kb + t + 4]);
                a[mt][3] = __float_as_uint(As[rb + g + 8][kb + t + 4]);
            }
#pragma unroll
            for (int nt = 0; nt < 8; ++nt) {
                int nb = wn * 64 + nt * 8;
                unsigned b0 = __float_as_uint(Bs[kb + t][nb + g]);
                unsigned b1 = __float_as_uint(Bs[kb + t + 4][nb + g]);
#pragma unroll
                for (int mt = 0; mt < 2; ++mt)
                    mma8(acc[mt][nt], a[mt][0], a[mt][1], a[mt][2], a[mt][3], b0, b1);
            }
        }
    }
#pragma unroll
    for (int mt = 0; mt < 2; ++mt) {
#pragma unroll
        for (int nt = 0; nt < 8; ++nt) {
            int r = row0 + wm * 32 + mt * 16 + g;
            int c = col0 + wn * 64 + nt * 8 + 2 * t;
            __stcs((float2*)&C[(size_t)r * N + c],
                   make_float2(acc[mt][nt][0], acc[mt][nt][1]));
            __stcs((float2*)&C[(size_t)(r + 8) * N + c],
                   make_float2(acc[mt][nt][2], acc[mt][nt][3]));
        }
    }
}

// ------- out-proj (R11-proven): 2 rows x 512 blocks ---------------------------
__global__ void __launch_bounds__(256) outproj_kernel(
    const float* __restrict__ A0, const float* __restrict__ A1,
    const float* __restrict__ B,
    const float* __restrict__ bias, float* __restrict__ C)
{
    __shared__ float As[2][512];
    const int tid = threadIdx.x;
    const int r0 = blockIdx.x * 2;
    {
        float4 a = __ldcs(&((const float4*)&A0[(size_t)r0 * 512])[tid]);
        float4 b = __ldcs(&((const float4*)&A1[(size_t)r0 * 512])[tid]);
        a.x += b.x; a.y += b.y; a.z += b.z; a.w += b.w;
        ((float4*)&As[0][0])[tid] = a;
    }
    __syncthreads();
    const int row = tid >> 7, c = tid & 127;
    const float* arow = As[row];
    float acc = bias[c];
    const float* bp = B + c;
#pragma unroll 8
    for (int k = 0; k < 512; k += 4) {
        float4 a = *(const float4*)&arow[k];
        acc += a.x * bp[(size_t)(k + 0) * 128];
        acc += a.y * bp[(size_t)(k + 1) * 128];
        acc += a.z * bp[(size_t)(k + 2) * 128];
        acc += a.w * bp[(size_t)(k + 3) * 128];
    }
    C[(size_t)(r0 + row) * 128 + c] = acc;
}

// ---------------- sim via tf32 mma: per (p-half, h, b) 64x256x32 --------------
__global__ void __launch_bounds__(256) sim_mma_kernel()
{
    __shared__ float As[64 * 34];   // [l][d]
    __shared__ float Bs[32 * 258];  // [d][p] (transposed)
    const int ph = blockIdx.x, h = blockIdx.y, b = blockIdx.z;
    const int tid = threadIdx.x;
    const int w = tid >> 5, lane = tid & 31, g = lane >> 2, t = lane & 3;

    for (int e = tid; e < 2048; e += 256) {
        int lr = e >> 5, d = e & 31;
        As[lr * 34 + d] = tf32r(__ldcs(&g_qk[((size_t)(b * 64 + lr)) * 512 + h * 32 + d]));
    }
    for (int e = tid; e < 8192; e += 256) {
        int p = e >> 5, d = e & 31;
        Bs[d * 258 + p] = tf32r(__ldcs(&g_cqk[((size_t)(b * 512 + ph * 256 + p)) * 512 + h * 32 + d]));
    }
    __syncthreads();

    float acc[4][4][4];
#pragma unroll
    for (int mi = 0; mi < 4; ++mi)
#pragma unroll
        for (int nt = 0; nt < 4; ++nt)
#pragma unroll
            for (int q = 0; q < 4; ++q) acc[mi][nt][q] = 0.f;

    const int n0 = w * 32;
#pragma unroll
    for (int kt = 0; kt < 4; ++kt) {
        const int kb = kt * 8;
        unsigned aF[4][4];
#pragma unroll
        for (int mi = 0; mi < 4; ++mi) {
            int rA = mi * 16;
            aF[mi][0] = __float_as_uint(As[(rA + g) * 34 + kb + t]);
            aF[mi][1] = __float_as_uint(As[(rA + g + 8) * 34 + kb + t]);
            aF[mi][2] = __float_as_uint(As[(rA + g) * 34 + kb + t + 4]);
            aF[mi][3] = __float_as_uint(As[(rA + g + 8) * 34 + kb + t + 4]);
        }
#pragma unroll
        for (int nt = 0; nt < 4; ++nt) {
            int nb = n0 + nt * 8;
            unsigned b0 = __float_as_uint(Bs[(kb + t) * 258 + nb + g]);
            unsigned b1 = __float_as_uint(Bs[(kb + t + 4) * 258 + nb + g]);
#pragma unroll
            for (int mi = 0; mi < 4; ++mi)
                mma8(acc[mi][nt], aF[mi][0], aF[mi][1], aF[mi][2], aF[mi][3], b0, b1);
        }
    }
    const float SCALE = 0.17677669529663687f; // 32^-0.5
#pragma unroll
    for (int mi = 0; mi < 4; ++mi)
#pragma unroll
        for (int nt = 0; nt < 4; ++nt) {
            int lr = mi * 16 + g;
            int pc = ph * 256 + n0 + nt * 8 + 2 * t;
            size_t base = (((size_t)(b * 16 + h)) * 64 + lr) * 512 + pc;
            __stcs((float2*)&g_sim[base],
                   make_float2(acc[mi][nt][0] * SCALE, acc[mi][nt][1] * SCALE));
            __stcs((float2*)&g_sim[base + (size_t)8 * 512],
                   make_float2(acc[mi][nt][2] * SCALE, acc[mi][nt][3] * SCALE));
        }
}

// ------- fused pairwise MLPs + softmax + distance path (FFMA2, 2 p/thread) ----
#define SM4_FLOATS (512 * 33 + 2048 + 2048 + 256 + 1024 + 64 + 16 + 32 + 1536 + 48 + 96)
__global__ void __launch_bounds__(256) pair_kernel(
    const float* __restrict__ xp, const float* __restrict__ xl,
    const float* __restrict__ w_mlp1, const float* __restrict__ w_mlp2,
    const float* __restrict__ b_mlp2, const float* __restrict__ sigma,
    const float* __restrict__ w_pe1, const float* __restrict__ b_pe1,
    const float* __restrict__ w_pe2, const float* __restrict__ b_pe2,
    const float* __restrict__ w_dis1, const float* __restrict__ b_dis1,
    const float* __restrict__ w_dis2, const float* __restrict__ b_dis2,
    float* __restrict__ out)
{
    extern __shared__ float sm[];
    float* lg    = sm;                 // 512*33 logits -> probs(c>=16)
    float* w1t   = lg + 512 * 33;      // [k][i] transposed w_mlp1, 64*32
    float* w2s   = w1t + 2048;         // w_mlp2 as-is, 64*32
    float* wpe1t = w2s + 2048;         // [k][i(pad4)], 64*4
    float* wpe2s = wpe1t + 256;        // w_pe2 as-is, 64*16
    float* bpe1s = wpe2s + 1024;       // 64
    float* bpe2s = bpe1s + 64;         // 16
    float* bm2s  = bpe2s + 16;         // 32
    float* xps   = bm2s + 32;          // [512][3] raw protein coords
    float* ods   = xps + 1536;         // [3][16]
    float* zs    = ods + 48;           // [3][32]

    const int tid = threadIdx.x;
    const int l = blockIdx.x, b = blockIdx.y;

    for (int e = tid; e < 2048; e += 256) { int i = e >> 6, k = e & 63; w1t[k * 32 + i] = w_mlp1[e]; }
    for (int e = tid; e < 2048; e += 256) w2s[e] = w_mlp2[e];
    if (tid < 192) { int i = tid >> 6, k = tid & 63; wpe1t[k * 4 + i] = w_pe1[tid]; }
    for (int e = tid; e < 1024; e += 256) wpe2s[e] = w_pe2[e];
    if (tid < 64) bpe1s[tid] = b_pe1[tid];
    if (tid < 16) bpe2s[tid] = b_pe2[tid];
    if (tid < 32) bm2s[tid]  = b_mlp2[tid];
    __syncthreads();

    const float sg = sigma[0];
    const float cpe = -0.5f / (sg * sg);
    const int rowl = b * 64 + l;
    const float xl0 = xl[rowl * 3 + 0], xl1 = xl[rowl * 3 + 1], xl2 = xl[rowl * 3 + 2];

    const int p0 = tid, p1 = tid + 256;

    // s pairs for both p: [0..7] sim heads, [8..15] dis_emb
    u64 sp0[16], sp1[16];
    {
        size_t base = (((size_t)b * 16) * 64 + l) * 512;
#pragma unroll
        for (int h2 = 0; h2 < 8; ++h2) {
            size_t o0 = base + (size_t)(2 * h2) * 64 * 512;
            size_t o1 = base + (size_t)(2 * h2 + 1) * 64 * 512;
            sp0[h2] = pk2(__ldcs(&g_sim[o0 + p0]), __ldcs(&g_sim[o1 + p0]));
            sp1[h2] = pk2(__ldcs(&g_sim[o0 + p1]), __ldcs(&g_sim[o1 + p1]));
        }
    }

    // positional-encoding MLP: 3 -> 64 (mish) -> 16, both p share weight loads
    {
        const float* xpr0 = xp + (size_t)(b * 512 + p0) * 3;
        const float* xpr1 = xp + (size_t)(b * 512 + p1) * 3;
        float xA0 = xpr0[0], xA1 = xpr0[1], xA2 = xpr0[2];
        float xB0 = xpr1[0], xB1 = xpr1[1], xB2 = xpr1[2];
        xps[p0 * 3 + 0] = xA0; xps[p0 * 3 + 1] = xA1; xps[p0 * 3 + 2] = xA2;
        xps[p1 * 3 + 0] = xB0; xps[p1 * 3 + 1] = xB1; xps[p1 * 3 + 2] = xB2;

        float peA0 = __expf(cpe * (xA0 - xl0));
        float peA1 = __expf(cpe * (xA1 - xl1));
        float peA2 = __expf(cpe * (xA2 - xl2));
        float peB0 = __expf(cpe * (xB0 - xl0));
        float peB1 = __expf(cpe * (xB1 - xl1));
        float peB2 = __expf(cpe * (xB2 - xl2));

        u64 deA[8], deB[8];
#pragma unroll
        for (int j = 0; j < 8; ++j) {
            u64 bb = pk2(bpe2s[2 * j], bpe2s[2 * j + 1]);
            deA[j] = bb; deB[j] = bb;
        }
#pragma unroll 2
        for (int k = 0; k < 64; ++k) {
            float w0 = wpe1t[k * 4], w1 = wpe1t[k * 4 + 1], w2 = wpe1t[k * 4 + 2];
            float bk = bpe1s[k];
            float hA = bk + peA0 * w0 + peA1 * w1 + peA2 * w2;
            float hB = bk + peB0 * w0 + peB1 * w1 + peB2 * w2;
            float mA = mishf(hA), mB = mishf(hB);
            u64 mA2 = pk2(mA, mA), mB2 = pk2(mB, mB);
            const ulonglong2* wr = (const ulonglong2*)(wpe2s + k * 16);
#pragma unroll
            for (int q = 0; q < 4; ++q) {
                ulonglong2 w = wr[q];
                deA[2 * q + 0] = ffma2(mA2, w.x, deA[2 * q + 0]);
                deA[2 * q + 1] = ffma2(mA2, w.y, deA[2 * q + 1]);
                deB[2 * q + 0] = ffma2(mB2, w.x, deB[2 * q + 0]);
                deB[2 * q + 1] = ffma2(mB2, w.y, deB[2 * q + 1]);
            }
        }
#pragma unroll
        for (int j = 0; j < 8; ++j) { sp0[8 + j] = deA[j]; sp1[8 + j] = deB[j]; }
    }

    // attention MLP: 32 -> 64 (mish) -> 32, single pass, split h-chains for ILP
    const u64 z2 = pk2(0.f, 0.f);
    u64 oA[16], oB[16];
#pragma unroll
    for (int j = 0; j < 16; ++j) {
        u64 bb = pk2(bm2s[2 * j], bm2s[2 * j + 1]);
        oA[j] = bb; oB[j] = bb;
    }
#pragma unroll 2
    for (int k = 0; k < 64; ++k) {
        const ulonglong2* w1r = (const ulonglong2*)(w1t + k * 32);
        u64 hA0 = z2, hA1 = z2, hB0 = z2, hB1 = z2;
#pragma unroll
        for (int q = 0; q < 4; ++q) {
            ulonglong2 w = w1r[q];
            hA0 = ffma2(sp0[2 * q + 0], w.x, hA0);
            hA0 = ffma2(sp0[2 * q + 1], w.y, hA0);
            hB0 = ffma2(sp1[2 * q + 0], w.x, hB0);
            hB0 = ffma2(sp1[2 * q + 1], w.y, hB0);
        }
#pragma unroll
        for (int q = 4; q < 8; ++q) {
            ulonglong2 w = w1r[q];
            hA1 = ffma2(sp0[2 * q + 0], w.x, hA1);
            hA1 = ffma2(sp0[2 * q + 1], w.y, hA1);
            hB1 = ffma2(sp1[2 * q + 0], w.x, hB1);
            hB1 = ffma2(sp1[2 * q + 1], w.y, hB1);
        }
        float2 a0 = up2(hA0), a1 = up2(hA1);
        float2 b0 = up2(hB0), b1 = up2(hB1);
        float mA = mishf((a0.x + a0.y) + (a1.x + a1.y));
        float mB = mishf((b0.x + b0.y) + (b1.x + b1.y));
        u64 mA2 = pk2(mA, mA), mB2 = pk2(mB, mB);
        const ulonglong2* w2r = (const ulonglong2*)(w2s + k * 32);
#pragma unroll
        for (int q = 0; q < 8; ++q) {
            ulonglong2 w = w2r[q];
            oA[2 * q + 0] = ffma2(mA2, w.x, oA[2 * q + 0]);
            oA[2 * q + 1] = ffma2(mA2, w.y, oA[2 * q + 1]);
            oB[2 * q + 0] = ffma2(mB2, w.x, oB[2 * q + 0]);
            oB[2 * q + 1] = ffma2(mB2, w.y, oB[2 * q + 1]);
        }
    }
#pragma unroll
    for (int j = 0; j < 16; ++j) {
        float2 vA = up2(oA[j]);
        float2 vB = up2(oB[j]);
        lg[p0 * 33 + 2 * j + 0] = vA.x;
        lg[p0 * 33 + 2 * j + 1] = vA.y;
        lg[p1 * 33 + 2 * j + 0] = vB.x;
        lg[p1 * 33 + 2 * j + 1] = vB.y;
    }
    __syncthreads();

    // softmax: warp w owns channels 4w..4w+3; c<16 -> g_probs, c>=16 -> lg smem
    const int w = tid >> 5, lane = tid & 31;
#pragma unroll
    for (int cc = 0; cc < 4; ++cc) {
        int c = w * 4 + cc;
        float mx = -3.4e38f;
#pragma unroll
        for (int i = 0; i < 16; ++i) mx = fmaxf(mx, lg[(lane + i * 32) * 33 + c]);
#pragma unroll
        for (int off = 16; off; off >>= 1) mx = fmaxf(mx, __shfl_xor_sync(0xffffffffu, mx, off));
        float ev[16]; float sum = 0.f;
#pragma unroll
        for (int i = 0; i < 16; ++i) {
            ev[i] = __expf(lg[(lane + i * 32) * 33 + c] - mx);
            sum += ev[i];
        }
#pragma unroll
        for (int off = 16; off; off >>= 1) sum += __shfl_xor_sync(0xffffffffu, sum, off);
        float inv = 1.0f / sum;
        if (c < 16) {
            size_t base = (((size_t)b * 32 + c) * 64 + l) * 512;
#pragma unroll
            for (int i = 0; i < 16; ++i)
                __stcs(&g_probs[base + lane + i * 32], ev[i] * inv);
        } else {
#pragma unroll
            for (int i = 0; i < 16; ++i) lg[(lane + i * 32) * 33 + c] = ev[i] * inv;
        }
    }
    __syncthreads();

    // ---- fused distance path: Σ_p prob·xp − xl, then tiny MLP into d_out ----
#pragma unroll
    for (int q = 0; q < 6; ++q) {
        int idx = w * 6 + q;
        int i = idx >> 4, h = idx & 15;
        float sum = 0.f;
#pragma unroll
        for (int it = 0; it < 16; ++it) {
            int p = lane + it * 32;
            sum += lg[p * 33 + 16 + h] * xps[p * 3 + i];
        }
#pragma unroll
        for (int off = 16; off; off >>= 1) sum += __shfl_xor_sync(0xffffffffu, sum, off);
        if (lane == 0) {
            float xli = (i == 0) ? xl0 : ((i == 1) ? xl1 : xl2);
            ods[i * 16 + h] = sum - xli;
        }
    }
    __syncthreads();
    if (tid < 96) {
        int i = tid >> 5, k = tid & 31;
        float hz = b_dis1[k];
#pragma unroll
        for (int j = 0; j < 16; ++j) hz += ods[i * 16 + j] * w_dis1[j * 32 + k];
        zs[i * 32 + k] = mishf(hz);
    }
    __syncthreads();
    if (tid < 48) {
        int i = tid / 16, h = tid % 16;
        float y = b_dis2[h];
#pragma unroll
        for (int k = 0; k < 32; ++k) y += zs[i * 32 + k] * w_dis2[k * 16 + h];
        out[OUT0 + (((size_t)b * 64 + l) * 3 + i) * 16 + h] = y;
    }
}

// ---- outagg via tf32 mma, k-split x2 + register-prefetch pipeline ------------
__global__ void __launch_bounds__(256) outagg_mma_kernel()
{
    __shared__ float As[64][68];
    __shared__ float Bs[64][40];
    const int b = blockIdx.x, h = blockIdx.y, z = blockIdx.z;
    const int tid = threadIdx.x;
    const int w = tid >> 5, lane = tid & 31, g = lane >> 2, t = lane & 3;
    const int mi = w >> 1, ni = w & 1;
    const int pbase = z * 256;
    float* outp = z ? g_outpre2 : g_outpre;

    float acc[2][4];
#pragma unroll
    for (int nt = 0; nt < 2; ++nt)
#pragma unroll
        for (int q = 0; q < 4; ++q) acc[nt][q] = 0.f;

    float4 pa[4], pb[2];
#pragma unroll
    for (int i = 0; i < 4; ++i) {
        int e = tid + i * 256;
        int lr = e >> 4, p4 = (e & 15) * 4;
        pa[i] = __ldcs((const float4*)&g_probs[(((size_t)b * 32 + h) * 64 + lr) * 512 + pbase + p4]);
    }
#pragma unroll
    for (int i = 0; i < 2; ++i) {
        int e = tid + i * 256;
        int p = e >> 3, d4 = (e & 7) * 4;
        pb[i] = __ldcs((const float4*)&g_cv[((size_t)(b * 512 + pbase + p)) * 512 + h * 32 + d4]);
    }

    for (int c4 = 0; c4 < 4; ++c4) {
        __syncthreads();
#pragma unroll
        for (int i = 0; i < 4; ++i) {
            int e = tid + i * 256;
            int lr = e >> 4, p4 = (e & 15) * 4;
            As[lr][p4 + 0] = tf32r(pa[i].x);
            As[lr][p4 + 1] = tf32r(pa[i].y);
            As[lr][p4 + 2] = tf32r(pa[i].z);
            As[lr][p4 + 3] = tf32r(pa[i].w);
        }
#pragma unroll
        for (int i = 0; i < 2; ++i) {
            int e = tid + i * 256;
            int p = e >> 3, d4 = (e & 7) * 4;
            Bs[p][d4 + 0] = tf32r(pb[i].x);
            Bs[p][d4 + 1] = tf32r(pb[i].y);
            Bs[p][d4 + 2] = tf32r(pb[i].z);
            Bs[p][d4 + 3] = tf32r(pb[i].w);
        }
        __syncthreads();
        if (c4 < 3) {
            int pc = pbase + (c4 + 1) * 64;
#pragma unroll
            for (int i = 0; i < 4; ++i) {
                int e = tid + i * 256;
                int lr = e >> 4, p4 = (e & 15) * 4;
                pa[i] = __ldcs((const float4*)&g_probs[(((size_t)b * 32 + h) * 64 + lr) * 512 + pc + p4]);
            }
#pragma unroll
            for (int i = 0; i < 2; ++i) {
                int e = tid + i * 256;
                int p = e >> 3, d4 = (e & 7) * 4;
                pb[i] = __ldcs((const float4*)&g_cv[((size_t)(b * 512 + pc + p)) * 512 + h * 32 + d4]);
            }
        }
#pragma unroll
        for (int kt = 0; kt < 8; ++kt) {
            const int kb = kt * 8;
            int rA = mi * 16;
            unsigned a0 = __float_as_uint(As[rA + g][kb + t]);
            unsigned a1 = __float_as_uint(As[rA + g + 8][kb + t]);
            unsigned a2 = __float_as_uint(As[rA + g][kb + t + 4]);
            unsigned a3 = __float_as_uint(As[rA + g + 8][kb + t + 4]);
#pragma unroll
            for (int nt = 0; nt < 2; ++nt) {
                int nb = ni * 16 + nt * 8;
                unsigned b0 = __float_as_uint(Bs[kb + t][nb + g]);
                unsigned b1 = __float_as_uint(Bs[kb + t + 4][nb + g]);
                mma8(acc[nt], a0, a1, a2, a3, b0, b1);
            }
        }
    }
#pragma unroll
    for (int nt = 0; nt < 2; ++nt) {
        int r = mi * 16 + g;
        int c = ni * 16 + nt * 8 + 2 * t;
        size_t base = ((size_t)(b * 64 + r)) * 512 + h * 32 + c;
        __stcs((float2*)&outp[base], make_float2(acc[nt][0], acc[nt][1]));
        __stcs((float2*)&outp[base + (size_t)8 * 512], make_float2(acc[nt][2], acc[nt][3]));
    }
}

// ---------------- launch -------------------------------------------------------
extern "C" void kernel_launch(void* const* d_in, const int* in_sizes, int n_in,
                              void* d_out, int out_size)
{
    (void)in_sizes; (void)n_in; (void)out_size;
    const float* h_ligand = (const float*)d_in[0];
    const float* context  = (const float*)d_in[1];
    const float* xp       = (const float*)d_in[2];
    const float* xl       = (const float*)d_in[3];
    const float* w_qk     = (const float*)d_in[4];
    // d_in[5] = w_v (unused by the reference)
    const float* w_cqk    = (const float*)d_in[6];
    const float* w_cv     = (const float*)d_in[7];
    const float* w_mlp1   = (const float*)d_in[8];
    const float* w_mlp2   = (const float*)d_in[9];
    const float* b_mlp2   = (const float*)d_in[10];
    const float* w_out    = (const float*)d_in[11];
    const float* b_out    = (const float*)d_in[12];
    const float* w_dis1   = (const float*)d_in[13];
    const float* b_dis1   = (const float*)d_in[14];
    const float* w_dis2   = (const float*)d_in[15];
    const float* b_dis2   = (const float*)d_in[16];
    const float* sigma    = (const float*)d_in[17];
    const float* w_pe1    = (const float*)d_in[18];
    const float* b_pe1    = (const float*)d_in[19];
    const float* w_pe2    = (const float*)d_in[20];
    const float* b_pe2    = (const float*)d_in[21];
    float* out = (float*)d_out;

    void *p_qk, *p_cqk, *p_cv, *p_outpre, *p_outpre2;
    cudaGetSymbolAddress(&p_qk, g_qk);
    cudaGetSymbolAddress(&p_cqk, g_cqk);
    cudaGetSymbolAddress(&p_cv, g_cv);
    cudaGetSymbolAddress(&p_outpre, g_outpre);
    cudaGetSymbolAddress(&p_outpre2, g_outpre2);

    // #1 all three projections in ONE launch (544 blocks, register-prefetch)
    tgemm_all<<<544, 256>>>(context, h_ligand, w_cqk, w_cv, w_qk,
                            (float*)p_cqk, (float*)p_cv, (float*)p_qk);
    // #2 similarity scores (tf32 mma)
    sim_mma_kernel<<<dim3(2, 16, 16), 256>>>();

    // #3 fused pairwise MLPs + softmax + distance path (banked R7 config)
    const int sm4_bytes = SM4_FLOATS * (int)sizeof(float);
    cudaFuncSetAttribute(pair_kernel, cudaFuncAttributeMaxDynamicSharedMemorySize, sm4_bytes);
    pair_kernel<<<dim3(64, 16), 256, sm4_bytes>>>(
        xp, xl, w_mlp1, w_mlp2, b_mlp2, sigma, w_pe1, b_pe1, w_pe2, b_pe2,
        w_dis1, b_dis1, w_dis2, b_dis2, out);

    // #4 context path: attn @ cv (tf32 mma, k-split x2, pipelined)
    outagg_mma_kernel<<<dim3(16, 16, 2), 256>>>();
    // #5 out-proj (+bias, sums 2 partials) into d_out — 512 blocks x 2 rows
    outproj_kernel<<<512, 256>>>((const float*)p_outpre, (const float*)p_outpre2,
                                 w_out, b_out, out);
}

// round 17
// speedup vs baseline: 1.1158x; 1.0001x over previous
#include <cuda_runtime.h>
#include <cstddef>

#define OUT0 131072 // 1024*128, offset of out_dis in d_out

typedef unsigned long long u64;

// ---------------- scratch (device globals; no allocation allowed) -------------
__device__ float g_qk[1024 * 512];            // [B*L][INNER]
__device__ float g_cqk[8192 * 512];           // [B*P][INNER]
__device__ float g_cv[8192 * 512];            // [B*P][INNER]
__device__ float g_sim[16 * 16 * 64 * 512];   // [b][h][l][p] (scaled)
__device__ float g_probs[16 * 32 * 64 * 512]; // [b][c][l][p] (only c<16 written)
__device__ float g_outpre[1024 * 512];        // partial 0 (p 0..255)
__device__ float g_outpre2[1024 * 512];       // partial 1 (p 256..511)

// mish(x) = x*tanh(softplus(x)) = x * u/(u+2), u = e^x*(e^x+2)  (exact identity)
__device__ __forceinline__ float mishf(float x) {
    float t = __expf(fminf(x, 8.0f));
    float u = t * (t + 2.0f);
    return x * __fdividef(u, u + 2.0f);
}

__device__ __forceinline__ float tf32r(float x) {
    unsigned u;
    asm("cvt.rna.tf32.f32 %0, %1;" : "=r"(u) : "f"(x));
    return __uint_as_float(u);
}

__device__ __forceinline__ void mma8(float* c, unsigned a0, unsigned a1,
                                     unsigned a2, unsigned a3,
                                     unsigned b0, unsigned b1) {
    asm volatile(
        "mma.sync.aligned.m16n8k8.row.col.f32.tf32.tf32.f32 "
        "{%0,%1,%2,%3},{%4,%5,%6,%7},{%8,%9},{%0,%1,%2,%3};"
        : "+f"(c[0]), "+f"(c[1]), "+f"(c[2]), "+f"(c[3])
        : "r"(a0), "r"(a1), "r"(a2), "r"(a3), "r"(b0), "r"(b1));
}

// ---- packed f32x2 helpers (Blackwell FFMA2 — only reachable via PTX) ---------
__device__ __forceinline__ u64 ffma2(u64 a, u64 b, u64 c) {
    u64 d;
    asm("fma.rn.f32x2 %0, %1, %2, %3;" : "=l"(d) : "l"(a), "l"(b), "l"(c));
    return d;
}
__device__ __forceinline__ u64 pk2(float x, float y) {
    u64 r;
    asm("mov.b64 %0, {%1, %2};" : "=l"(r) : "f"(x), "f"(y));
    return r;
}
__device__ __forceinline__ float2 up2(u64 v) {
    float2 r;
    asm("mov.b64 {%0, %1}, %2;" : "=f"(r.x), "=f"(r.y) : "l"(v));
    return r;
}

// ------ unified tf32 GEMM launch: blocks 0..511 cqk|cv (K=256), 512..543 qk ----
// Software-pipelined: next k-slab's global loads issued before the mma phase.
__global__ void __launch_bounds__(256, 2) tgemm_all(
    const float* __restrict__ ctx, const float* __restrict__ hlig,
    const float* __restrict__ w_cqk, const float* __restrict__ w_cv,
    const float* __restrict__ w_qk,
    float* __restrict__ cqk, float* __restrict__ cv, float* __restrict__ qk)
{
    __shared__ float As[128][36];
    __shared__ float Bs[32][136];
    const int tid = threadIdx.x;
    const int lane = tid & 31, warp = tid >> 5;
    const int wm = warp >> 1, wn = warp & 1;
    const int g = lane >> 2, t = lane & 3;
    const int N = 512;

    int bid = blockIdx.x;
    const float* A; const float* Bm; float* C;
    int row0, col0, K;
    if (bid < 512) {
        row0 = (bid >> 3) * 128; col0 = (bid & 7) * 128;
        A = ctx; K = 256;
        if (col0 >= 512) { Bm = w_cv; C = cv; col0 -= 512; }
        else             { Bm = w_cqk; C = cqk; }
    } else {
        int b2 = bid - 512;
        row0 = (b2 >> 2) * 128; col0 = (b2 & 3) * 128;
        A = hlig; Bm = w_qk; C = qk; K = 128;
    }

    float acc[2][8][4];
#pragma unroll
    for (int mt = 0; mt < 2; ++mt)
#pragma unroll
        for (int nt = 0; nt < 8; ++nt)
#pragma unroll
            for (int q = 0; q < 4; ++q) acc[mt][nt][q] = 0.f;

    float4 va[4], vb[4];
    // prologue: load slab 0
#pragma unroll
    for (int i = 0; i < 4; ++i) {
        int f4 = tid + i * 256;
        int r = f4 >> 3, kc = (f4 & 7) * 4;
        va[i] = *(const float4*)&A[(size_t)(row0 + r) * K + kc];
        int kk = f4 >> 5, nc = (f4 & 31) * 4;
        vb[i] = *(const float4*)&Bm[(size_t)kk * N + col0 + nc];
    }

    for (int k0 = 0; k0 < K; k0 += 32) {
        __syncthreads();
#pragma unroll
        for (int i = 0; i < 4; ++i) {
            int f4 = tid + i * 256;
            int r = f4 >> 3, kc = (f4 & 7) * 4;
            As[r][kc + 0] = tf32r(va[i].x);
            As[r][kc + 1] = tf32r(va[i].y);
            As[r][kc + 2] = tf32r(va[i].z);
            As[r][kc + 3] = tf32r(va[i].w);
            int kk = f4 >> 5, nc = (f4 & 31) * 4;
            Bs[kk][nc + 0] = tf32r(vb[i].x);
            Bs[kk][nc + 1] = tf32r(vb[i].y);
            Bs[kk][nc + 2] = tf32r(vb[i].z);
            Bs[kk][nc + 3] = tf32r(vb[i].w);
        }
        __syncthreads();
        // prefetch next slab while mma runs
        if (k0 + 32 < K) {
            int kn = k0 + 32;
#pragma unroll
            for (int i = 0; i < 4; ++i) {
                int f4 = tid + i * 256;
                int r = f4 >> 3, kc = (f4 & 7) * 4;
                va[i] = *(const float4*)&A[(size_t)(row0 + r) * K + kn + kc];
                int kk = f4 >> 5, nc = (f4 & 31) * 4;
                vb[i] = *(const float4*)&Bm[(size_t)(kn + kk) * N + col0 + nc];
            }
        }
#pragma unroll
        for (int ks = 0; ks < 4; ++ks) {
            const int kb = ks * 8;
            unsigned a[2][4];
#pragma unroll
            for (int mt = 0; mt < 2; ++mt) {
                int rb = wm * 32 + mt * 16;
                a[mt][0] = __float_as_uint(As[rb + g][kb + t]);
                a[mt][1] = __float_as_uint(As[rb + g + 8][kb + t]);
                a[mt][2] = __float_as_uint(As[rb + g][kb + t + 4]);
                a[mt][3] = __float_as_uint(As[rb + g + 8][kb + t + 4]);
            }
#pragma unroll
            for (int nt = 0; nt < 8; ++nt) {
                int nb = wn * 64 + nt * 8;
                unsigned b0 = __float_as_uint(Bs[kb + t][nb + g]);
                unsigned b1 = __float_as_uint(Bs[kb + t + 4][nb + g]);
#pragma unroll
                for (int mt = 0; mt < 2; ++mt)
                    mma8(acc[mt][nt], a[mt][0], a[mt][1], a[mt][2], a[mt][3], b0, b1);
            }
        }
    }
#pragma unroll
    for (int mt = 0; mt < 2; ++mt) {
#pragma unroll
        for (int nt = 0; nt < 8; ++nt) {
            int r = row0 + wm * 32 + mt * 16 + g;
            int c = col0 + wn * 64 + nt * 8 + 2 * t;
            __stcs((float2*)&C[(size_t)r * N + c],
                   make_float2(acc[mt][nt][0], acc[mt][nt][1]));
            __stcs((float2*)&C[(size_t)(r + 8) * N + c],
                   make_float2(acc[mt][nt][2], acc[mt][nt][3]));
        }
    }
}

// ------- out-proj (R11-proven): 2 rows x 512 blocks ---------------------------
__global__ void __launch_bounds__(256) outproj_kernel(
    const float* __restrict__ A0, const float* __restrict__ A1,
    const float* __restrict__ B,
    const float* __restrict__ bias, float* __restrict__ C)
{
    __shared__ float As[2][512];
    const int tid = threadIdx.x;
    const int r0 = blockIdx.x * 2;
    {
        float4 a = __ldcs(&((const float4*)&A0[(size_t)r0 * 512])[tid]);
        float4 b = __ldcs(&((const float4*)&A1[(size_t)r0 * 512])[tid]);
        a.x += b.x; a.y += b.y; a.z += b.z; a.w += b.w;
        ((float4*)&As[0][0])[tid] = a;
    }
    __syncthreads();
    const int row = tid >> 7, c = tid & 127;
    const float* arow = As[row];
    float acc = bias[c];
    const float* bp = B + c;
#pragma unroll 8
    for (int k = 0; k < 512; k += 4) {
        float4 a = *(const float4*)&arow[k];
        acc += a.x * bp[(size_t)(k + 0) * 128];
        acc += a.y * bp[(size_t)(k + 1) * 128];
        acc += a.z * bp[(size_t)(k + 2) * 128];
        acc += a.w * bp[(size_t)(k + 3) * 128];
    }
    C[(size_t)(r0 + row) * 128 + c] = acc;
}

// ---------------- sim via tf32 mma: per (p-half, h, b) 64x256x32 --------------
__global__ void __launch_bounds__(256) sim_mma_kernel()
{
    __shared__ float As[64 * 34];   // [l][d]
    __shared__ float Bs[32 * 258];  // [d][p] (transposed)
    const int ph = blockIdx.x, h = blockIdx.y, b = blockIdx.z;
    const int tid = threadIdx.x;
    const int w = tid >> 5, lane = tid & 31, g = lane >> 2, t = lane & 3;

    for (int e = tid; e < 2048; e += 256) {
        int lr = e >> 5, d = e & 31;
        As[lr * 34 + d] = tf32r(__ldcs(&g_qk[((size_t)(b * 64 + lr)) * 512 + h * 32 + d]));
    }
    for (int e = tid; e < 8192; e += 256) {
        int p = e >> 5, d = e & 31;
        Bs[d * 258 + p] = tf32r(__ldcs(&g_cqk[((size_t)(b * 512 + ph * 256 + p)) * 512 + h * 32 + d]));
    }
    __syncthreads();

    float acc[4][4][4];
#pragma unroll
    for (int mi = 0; mi < 4; ++mi)
#pragma unroll
        for (int nt = 0; nt < 4; ++nt)
#pragma unroll
            for (int q = 0; q < 4; ++q) acc[mi][nt][q] = 0.f;

    const int n0 = w * 32;
#pragma unroll
    for (int kt = 0; kt < 4; ++kt) {
        const int kb = kt * 8;
        unsigned aF[4][4];
#pragma unroll
        for (int mi = 0; mi < 4; ++mi) {
            int rA = mi * 16;
            aF[mi][0] = __float_as_uint(As[(rA + g) * 34 + kb + t]);
            aF[mi][1] = __float_as_uint(As[(rA + g + 8) * 34 + kb + t]);
            aF[mi][2] = __float_as_uint(As[(rA + g) * 34 + kb + t + 4]);
            aF[mi][3] = __float_as_uint(As[(rA + g + 8) * 34 + kb + t + 4]);
        }
#pragma unroll
        for (int nt = 0; nt < 4; ++nt) {
            int nb = n0 + nt * 8;
            unsigned b0 = __float_as_uint(Bs[(kb + t) * 258 + nb + g]);
            unsigned b1 = __float_as_uint(Bs[(kb + t + 4) * 258 + nb + g]);
#pragma unroll
            for (int mi = 0; mi < 4; ++mi)
                mma8(acc[mi][nt], aF[mi][0], aF[mi][1], aF[mi][2], aF[mi][3], b0, b1);
        }
    }
    const float SCALE = 0.17677669529663687f; // 32^-0.5
#pragma unroll
    for (int mi = 0; mi < 4; ++mi)
#pragma unroll
        for (int nt = 0; nt < 4; ++nt) {
            int lr = mi * 16 + g;
            int pc = ph * 256 + n0 + nt * 8 + 2 * t;
            size_t base = (((size_t)(b * 16 + h)) * 64 + lr) * 512 + pc;
            __stcs((float2*)&g_sim[base],
                   make_float2(acc[mi][nt][0] * SCALE, acc[mi][nt][1] * SCALE));
            __stcs((float2*)&g_sim[base + (size_t)8 * 512],
                   make_float2(acc[mi][nt][2] * SCALE, acc[mi][nt][3] * SCALE));
        }
}

// ------- fused pairwise MLPs + softmax + distance path (FFMA2, 2 p/thread) ----
#define SM4_FLOATS (512 * 33 + 2048 + 2048 + 256 + 1024 + 64 + 16 + 32 + 1536 + 48 + 96)
__global__ void __launch_bounds__(256) pair_kernel(
    const float* __restrict__ xp, const float* __restrict__ xl,
    const float* __restrict__ w_mlp1, const float* __restrict__ w_mlp2,
    const float* __restrict__ b_mlp2, const float* __restrict__ sigma,
    const float* __restrict__ w_pe1, const float* __restrict__ b_pe1,
    const float* __restrict__ w_pe2, const float* __restrict__ b_pe2,
    const float* __restrict__ w_dis1, const float* __restrict__ b_dis1,
    const float* __restrict__ w_dis2, const float* __restrict__ b_dis2,
    float* __restrict__ out)
{
    extern __shared__ float sm[];
    float* lg    = sm;                 // 512*33 logits -> probs(c>=16)
    float* w1t   = lg + 512 * 33;      // [k][i] transposed w_mlp1, 64*32
    float* w2s   = w1t + 2048;         // w_mlp2 as-is, 64*32
    float* wpe1t = w2s + 2048;         // [k][i(pad4)], 64*4
    float* wpe2s = wpe1t + 256;        // w_pe2 as-is, 64*16
    float* bpe1s = wpe2s + 1024;       // 64
    float* bpe2s = bpe1s + 64;         // 16
    float* bm2s  = bpe2s + 16;         // 32
    float* xps   = bm2s + 32;          // [512][3] raw protein coords
    float* ods   = xps + 1536;         // [3][16]
    float* zs    = ods + 48;           // [3][32]

    const int tid = threadIdx.x;
    const int l = blockIdx.x, b = blockIdx.y;

    for (int e = tid; e < 2048; e += 256) { int i = e >> 6, k = e & 63; w1t[k * 32 + i] = w_mlp1[e]; }
    for (int e = tid; e < 2048; e += 256) w2s[e] = w_mlp2[e];
    if (tid < 192) { int i = tid >> 6, k = tid & 63; wpe1t[k * 4 + i] = w_pe1[tid]; }
    for (int e = tid; e < 1024; e += 256) wpe2s[e] = w_pe2[e];
    if (tid < 64) bpe1s[tid] = b_pe1[tid];
    if (tid < 16) bpe2s[tid] = b_pe2[tid];
    if (tid < 32) bm2s[tid]  = b_mlp2[tid];
    __syncthreads();

    const float sg = sigma[0];
    const float cpe = -0.5f / (sg * sg);
    const int rowl = b * 64 + l;
    const float xl0 = xl[rowl * 3 + 0], xl1 = xl[rowl * 3 + 1], xl2 = xl[rowl * 3 + 2];

    const int p0 = tid, p1 = tid + 256;

    // s pairs for both p: [0..7] sim heads, [8..15] dis_emb
    u64 sp0[16], sp1[16];
    {
        size_t base = (((size_t)b * 16) * 64 + l) * 512;
#pragma unroll
        for (int h2 = 0; h2 < 8; ++h2) {
            size_t o0 = base + (size_t)(2 * h2) * 64 * 512;
            size_t o1 = base + (size_t)(2 * h2 + 1) * 64 * 512;
            sp0[h2] = pk2(__ldcs(&g_sim[o0 + p0]), __ldcs(&g_sim[o1 + p0]));
            sp1[h2] = pk2(__ldcs(&g_sim[o0 + p1]), __ldcs(&g_sim[o1 + p1]));
        }
    }

    // positional-encoding MLP: 3 -> 64 (mish) -> 16, both p share weight loads
    {
        const float* xpr0 = xp + (size_t)(b * 512 + p0) * 3;
        const float* xpr1 = xp + (size_t)(b * 512 + p1) * 3;
        float xA0 = xpr0[0], xA1 = xpr0[1], xA2 = xpr0[2];
        float xB0 = xpr1[0], xB1 = xpr1[1], xB2 = xpr1[2];
        xps[p0 * 3 + 0] = xA0; xps[p0 * 3 + 1] = xA1; xps[p0 * 3 + 2] = xA2;
        xps[p1 * 3 + 0] = xB0; xps[p1 * 3 + 1] = xB1; xps[p1 * 3 + 2] = xB2;

        float peA0 = __expf(cpe * (xA0 - xl0));
        float peA1 = __expf(cpe * (xA1 - xl1));
        float peA2 = __expf(cpe * (xA2 - xl2));
        float peB0 = __expf(cpe * (xB0 - xl0));
        float peB1 = __expf(cpe * (xB1 - xl1));
        float peB2 = __expf(cpe * (xB2 - xl2));

        u64 deA[8], deB[8];
#pragma unroll
        for (int j = 0; j < 8; ++j) {
            u64 bb = pk2(bpe2s[2 * j], bpe2s[2 * j + 1]);
            deA[j] = bb; deB[j] = bb;
        }
#pragma unroll 2
        for (int k = 0; k < 64; ++k) {
            float w0 = wpe1t[k * 4], w1 = wpe1t[k * 4 + 1], w2 = wpe1t[k * 4 + 2];
            float bk = bpe1s[k];
            float hA = bk + peA0 * w0 + peA1 * w1 + peA2 * w2;
            float hB = bk + peB0 * w0 + peB1 * w1 + peB2 * w2;
            float mA = mishf(hA), mB = mishf(hB);
            u64 mA2 = pk2(mA, mA), mB2 = pk2(mB, mB);
            const ulonglong2* wr = (const ulonglong2*)(wpe2s + k * 16);
#pragma unroll
            for (int q = 0; q < 4; ++q) {
                ulonglong2 w = wr[q];
                deA[2 * q + 0] = ffma2(mA2, w.x, deA[2 * q + 0]);
                deA[2 * q + 1] = ffma2(mA2, w.y, deA[2 * q + 1]);
                deB[2 * q + 0] = ffma2(mB2, w.x, deB[2 * q + 0]);
                deB[2 * q + 1] = ffma2(mB2, w.y, deB[2 * q + 1]);
            }
        }
#pragma unroll
        for (int j = 0; j < 8; ++j) { sp0[8 + j] = deA[j]; sp1[8 + j] = deB[j]; }
    }

    // attention MLP: 32 -> 64 (mish) -> 32, single pass, split h-chains for ILP
    const u64 z2 = pk2(0.f, 0.f);
    u64 oA[16], oB[16];
#pragma unroll
    for (int j = 0; j < 16; ++j) {
        u64 bb = pk2(bm2s[2 * j], bm2s[2 * j + 1]);
        oA[j] = bb; oB[j] = bb;
    }
#pragma unroll 2
    for (int k = 0; k < 64; ++k) {
        const ulonglong2* w1r = (const ulonglong2*)(w1t + k * 32);
        u64 hA0 = z2, hA1 = z2, hB0 = z2, hB1 = z2;
#pragma unroll
        for (int q = 0; q < 4; ++q) {
            ulonglong2 w = w1r[q];
            hA0 = ffma2(sp0[2 * q + 0], w.x, hA0);
            hA0 = ffma2(sp0[2 * q + 1], w.y, hA0);
            hB0 = ffma2(sp1[2 * q + 0], w.x, hB0);
            hB0 = ffma2(sp1[2 * q + 1], w.y, hB0);
        }
#pragma unroll
        for (int q = 4; q < 8; ++q) {
            ulonglong2 w = w1r[q];
            hA1 = ffma2(sp0[2 * q + 0], w.x, hA1);
            hA1 = ffma2(sp0[2 * q + 1], w.y, hA1);
            hB1 = ffma2(sp1[2 * q + 0], w.x, hB1);
            hB1 = ffma2(sp1[2 * q + 1], w.y, hB1);
        }
        float2 a0 = up2(hA0), a1 = up2(hA1);
        float2 b0 = up2(hB0), b1 = up2(hB1);
        float mA = mishf((a0.x + a0.y) + (a1.x + a1.y));
        float mB = mishf((b0.x + b0.y) + (b1.x + b1.y));
        u64 mA2 = pk2(mA, mA), mB2 = pk2(mB, mB);
        const ulonglong2* w2r = (const ulonglong2*)(w2s + k * 32);
#pragma unroll
        for (int q = 0; q < 8; ++q) {
            ulonglong2 w = w2r[q];
            oA[2 * q + 0] = ffma2(mA2, w.x, oA[2 * q + 0]);
            oA[2 * q + 1] = ffma2(mA2, w.y, oA[2 * q + 1]);
            oB[2 * q + 0] = ffma2(mB2, w.x, oB[2 * q + 0]);
            oB[2 * q + 1] = ffma2(mB2, w.y, oB[2 * q + 1]);
        }
    }
#pragma unroll
    for (int j = 0; j < 16; ++j) {
        float2 vA = up2(oA[j]);
        float2 vB = up2(oB[j]);
        lg[p0 * 33 + 2 * j + 0] = vA.x;
        lg[p0 * 33 + 2 * j + 1] = vA.y;
        lg[p1 * 33 + 2 * j + 0] = vB.x;
        lg[p1 * 33 + 2 * j + 1] = vB.y;
    }
    __syncthreads();

    // softmax: warp w owns channels 4w..4w+3; c<16 -> g_probs (L2-resident,
    // consumed immediately by outagg), c>=16 -> lg smem
    const int w = tid >> 5, lane = tid & 31;
#pragma unroll
    for (int cc = 0; cc < 4; ++cc) {
        int c = w * 4 + cc;
        float mx = -3.4e38f;
#pragma unroll
        for (int i = 0; i < 16; ++i) mx = fmaxf(mx, lg[(lane + i * 32) * 33 + c]);
#pragma unroll
        for (int off = 16; off; off >>= 1) mx = fmaxf(mx, __shfl_xor_sync(0xffffffffu, mx, off));
        float ev[16]; float sum = 0.f;
#pragma unroll
        for (int i = 0; i < 16; ++i) {
            ev[i] = __expf(lg[(lane + i * 32) * 33 + c] - mx);
            sum += ev[i];
        }
#pragma unroll
        for (int off = 16; off; off >>= 1) sum += __shfl_xor_sync(0xffffffffu, sum, off);
        float inv = 1.0f / sum;
        if (c < 16) {
            size_t base = (((size_t)b * 32 + c) * 64 + l) * 512;
#pragma unroll
            for (int i = 0; i < 16; ++i)
                g_probs[base + lane + i * 32] = ev[i] * inv;
        } else {
#pragma unroll
            for (int i = 0; i < 16; ++i) lg[(lane + i * 32) * 33 + c] = ev[i] * inv;
        }
    }
    __syncthreads();

    // ---- fused distance path: Σ_p prob·xp − xl, then tiny MLP into d_out ----
#pragma unroll
    for (int q = 0; q < 6; ++q) {
        int idx = w * 6 + q;
        int i = idx >> 4, h = idx & 15;
        float sum = 0.f;
#pragma unroll
        for (int it = 0; it < 16; ++it) {
            int p = lane + it * 32;
            sum += lg[p * 33 + 16 + h] * xps[p * 3 + i];
        }
#pragma unroll
        for (int off = 16; off; off >>= 1) sum += __shfl_xor_sync(0xffffffffu, sum, off);
        if (lane == 0) {
            float xli = (i == 0) ? xl0 : ((i == 1) ? xl1 : xl2);
            ods[i * 16 + h] = sum - xli;
        }
    }
    __syncthreads();
    if (tid < 96) {
        int i = tid >> 5, k = tid & 31;
        float hz = b_dis1[k];
#pragma unroll
        for (int j = 0; j < 16; ++j) hz += ods[i * 16 + j] * w_dis1[j * 32 + k];
        zs[i * 32 + k] = mishf(hz);
    }
    __syncthreads();
    if (tid < 48) {
        int i = tid / 16, h = tid % 16;
        float y = b_dis2[h];
#pragma unroll
        for (int k = 0; k < 32; ++k) y += zs[i * 32 + k] * w_dis2[k * 16 + h];
        out[OUT0 + (((size_t)b * 64 + l) * 3 + i) * 16 + h] = y;
    }
}

// ---- outagg via tf32 mma, k-split x2 + register-prefetch pipeline ------------
__global__ void __launch_bounds__(256) outagg_mma_kernel()
{
    __shared__ float As[64][68];
    __shared__ float Bs[64][40];
    const int b = blockIdx.x, h = blockIdx.y, z = blockIdx.z;
    const int tid = threadIdx.x;
    const int w = tid >> 5, lane = tid & 31, g = lane >> 2, t = lane & 3;
    const int mi = w >> 1, ni = w & 1;
    const int pbase = z * 256;
    float* outp = z ? g_outpre2 : g_outpre;

    float acc[2][4];
#pragma unroll
    for (int nt = 0; nt < 2; ++nt)
#pragma unroll
        for (int q = 0; q < 4; ++q) acc[nt][q] = 0.f;

    float4 pa[4], pb[2];
#pragma unroll
    for (int i = 0; i < 4; ++i) {
        int e = tid + i * 256;
        int lr = e >> 4, p4 = (e & 15) * 4;
        pa[i] = __ldcs((const float4*)&g_probs[(((size_t)b * 32 + h) * 64 + lr) * 512 + pbase + p4]);
    }
#pragma unroll
    for (int i = 0; i < 2; ++i) {
        int e = tid + i * 256;
        int p = e >> 3, d4 = (e & 7) * 4;
        pb[i] = __ldcs((const float4*)&g_cv[((size_t)(b * 512 + pbase + p)) * 512 + h * 32 + d4]);
    }

    for (int c4 = 0; c4 < 4; ++c4) {
        __syncthreads();
#pragma unroll
        for (int i = 0; i < 4; ++i) {
            int e = tid + i * 256;
            int lr = e >> 4, p4 = (e & 15) * 4;
            As[lr][p4 + 0] = tf32r(pa[i].x);
            As[lr][p4 + 1] = tf32r(pa[i].y);
            As[lr][p4 + 2] = tf32r(pa[i].z);
            As[lr][p4 + 3] = tf32r(pa[i].w);
        }
#pragma unroll
        for (int i = 0; i < 2; ++i) {
            int e = tid + i * 256;
            int p = e >> 3, d4 = (e & 7) * 4;
            Bs[p][d4 + 0] = tf32r(pb[i].x);
            Bs[p][d4 + 1] = tf32r(pb[i].y);
            Bs[p][d4 + 2] = tf32r(pb[i].z);
            Bs[p][d4 + 3] = tf32r(pb[i].w);
        }
        __syncthreads();
        if (c4 < 3) {
            int pc = pbase + (c4 + 1) * 64;
#pragma unroll
            for (int i = 0; i < 4; ++i) {
                int e = tid + i * 256;
                int lr = e >> 4, p4 = (e & 15) * 4;
                pa[i] = __ldcs((const float4*)&g_probs[(((size_t)b * 32 + h) * 64 + lr) * 512 + pc + p4]);
            }
#pragma unroll
            for (int i = 0; i < 2; ++i) {
                int e = tid + i * 256;
                int p = e >> 3, d4 = (e & 7) * 4;
                pb[i] = __ldcs((const float4*)&g_cv[((size_t)(b * 512 + pc + p)) * 512 + h * 32 + d4]);
            }
        }
#pragma unroll
        for (int kt = 0; kt < 8; ++kt) {
            const int kb = kt * 8;
            int rA = mi * 16;
            unsigned a0 = __float_as_uint(As[rA + g][kb + t]);
            unsigned a1 = __float_as_uint(As[rA + g + 8][kb + t]);
            unsigned a2 = __float_as_uint(As[rA + g][kb + t + 4]);
            unsigned a3 = __float_as_uint(As[rA + g + 8][kb + t + 4]);
#pragma unroll
            for (int nt = 0; nt < 2; ++nt) {
                int nb = ni * 16 + nt * 8;
                unsigned b0 = __float_as_uint(Bs[kb + t][nb + g]);
                unsigned b1 = __float_as_uint(Bs[kb + t + 4][nb + g]);
                mma8(acc[nt], a0, a1, a2, a3, b0, b1);
            }
        }
    }
#pragma unroll
    for (int nt = 0; nt < 2; ++nt) {
        int r = mi * 16 + g;
        int c = ni * 16 + nt * 8 + 2 * t;
        size_t base = ((size_t)(b * 64 + r)) * 512 + h * 32 + c;
        __stcs((float2*)&outp[base], make_float2(acc[nt][0], acc[nt][1]));
        __stcs((float2*)&outp[base + (size_t)8 * 512], make_float2(acc[nt][2], acc[nt][3]));
    }
}

// ---------------- launch -------------------------------------------------------
extern "C" void kernel_launch(void* const* d_in, const int* in_sizes, int n_in,
                              void* d_out, int out_size)
{
    (void)in_sizes; (void)n_in; (void)out_size;
    const float* h_ligand = (const float*)d_in[0];
    const float* context  = (const float*)d_in[1];
    const float* xp       = (const float*)d_in[2];
    const float* xl       = (const float*)d_in[3];
    const float* w_qk     = (const float*)d_in[4];
    // d_in[5] = w_v (unused by the reference)
    const float* w_cqk    = (const float*)d_in[6];
    const float* w_cv     = (const float*)d_in[7];
    const float* w_mlp1   = (const float*)d_in[8];
    const float* w_mlp2   = (const float*)d_in[9];
    const float* b_mlp2   = (const float*)d_in[10];
    const float* w_out    = (const float*)d_in[11];
    const float* b_out    = (const float*)d_in[12];
    const float* w_dis1   = (const float*)d_in[13];
    const float* b_dis1   = (const float*)d_in[14];
    const float* w_dis2   = (const float*)d_in[15];
    const float* b_dis2   = (const float*)d_in[16];
    const float* sigma    = (const float*)d_in[17];
    const float* w_pe1    = (const float*)d_in[18];
    const float* b_pe1    = (const float*)d_in[19];
    const float* w_pe2    = (const float*)d_in[20];
    const float* b_pe2    = (const float*)d_in[21];
    float* out = (float*)d_out;

    void *p_qk, *p_cqk, *p_cv, *p_outpre, *p_outpre2;
    cudaGetSymbolAddress(&p_qk, g_qk);
    cudaGetSymbolAddress(&p_cqk, g_cqk);
    cudaGetSymbolAddress(&p_cv, g_cv);
    cudaGetSymbolAddress(&p_outpre, g_outpre);
    cudaGetSymbolAddress(&p_outpre2, g_outpre2);

    // #1 all three projections in ONE launch (544 blocks, register-prefetch)
    tgemm_all<<<544, 256>>>(context, h_ligand, w_cqk, w_cv, w_qk,
                            (float*)p_cqk, (float*)p_cv, (float*)p_qk);
    // #2 similarity scores (tf32 mma)
    sim_mma_kernel<<<dim3(2, 16, 16), 256>>>();

    // #3 fused pairwise MLPs + softmax + distance path (banked R7 config)
    const int sm4_bytes = SM4_FLOATS * (int)sizeof(float);
    cudaFuncSetAttribute(pair_kernel, cudaFuncAttributeMaxDynamicSharedMemorySize, sm4_bytes);
    pair_kernel<<<dim3(64, 16), 256, sm4_bytes>>>(
        xp, xl, w_mlp1, w_mlp2, b_mlp2, sigma, w_pe1, b_pe1, w_pe2, b_pe2,
        w_dis1, b_dis1, w_dis2, b_dis2, out);

    // #4 context path: attn @ cv (tf32 mma, k-split x2, pipelined)
    outagg_mma_kernel<<<dim3(16, 16, 2), 256>>>();
    // #5 out-proj (+bias, sums 2 partials) into d_out — 512 blocks x 2 rows
    outproj_kernel<<<512, 256>>>((const float*)p_outpre, (const float*)p_outpre2,
                                 w_out, b_out, out);
}